// round 1
// baseline (speedup 1.0000x reference)
#include <cuda_runtime.h>

// Problem constants
#define Bv   2
#define Sv   2048
#define Hv   16
#define Dv   64
#define Ev   1024
#define MTOK (Bv * Sv)   // 4096 tokens

// Scratch (device globals — no allocation allowed)
__device__ float g_Q [MTOK * Ev];
__device__ float g_K [MTOK * Ev];
__device__ float g_V [MTOK * Ev];
__device__ float g_AO[MTOK * Ev];

// ---------------------------------------------------------------------------
// SGEMM: C[M,N] = A[M,K] * B[K,N], row-major. M%128==0, N%128==0, K%8==0.
// 128x128 block tile, BK=8, 256 threads, 8x8 per-thread register tile.
// ---------------------------------------------------------------------------
__global__ __launch_bounds__(256) void sgemm128(const float* __restrict__ A,
                                                const float* __restrict__ B,
                                                float* __restrict__ C,
                                                int M, int N, int K) {
    __shared__ float As[8][128];
    __shared__ float Bs[8][128];

    const int tid  = threadIdx.x;
    const int brow = blockIdx.y;
    const int bcol = blockIdx.x;

    const float* Ab = A + (size_t)brow * 128 * K;
    const float* Bb = B + (size_t)bcol * 128;

    const int arow   = tid >> 1;          // 0..127
    const int acol   = (tid & 1) * 4;     // 0 or 4
    const int brow_l = tid >> 5;          // 0..7
    const int bcol_l = (tid & 31) * 4;    // 0..124
    const int tr     = tid >> 4;          // 0..15
    const int tc     = tid & 15;          // 0..15

    float acc[8][8];
#pragma unroll
    for (int i = 0; i < 8; i++)
#pragma unroll
        for (int j = 0; j < 8; j++) acc[i][j] = 0.0f;

    for (int k0 = 0; k0 < K; k0 += 8) {
        float4 av = *(const float4*)&Ab[(size_t)arow * K + k0 + acol];
        As[acol + 0][arow] = av.x;
        As[acol + 1][arow] = av.y;
        As[acol + 2][arow] = av.z;
        As[acol + 3][arow] = av.w;
        *(float4*)&Bs[brow_l][bcol_l] =
            *(const float4*)&Bb[(size_t)(k0 + brow_l) * N + bcol_l];
        __syncthreads();

#pragma unroll
        for (int kk = 0; kk < 8; kk++) {
            float4 a0 = *(const float4*)&As[kk][tr * 8];
            float4 a1 = *(const float4*)&As[kk][tr * 8 + 4];
            float4 b0 = *(const float4*)&Bs[kk][tc * 8];
            float4 b1 = *(const float4*)&Bs[kk][tc * 8 + 4];
            float a[8] = {a0.x, a0.y, a0.z, a0.w, a1.x, a1.y, a1.z, a1.w};
            float b[8] = {b0.x, b0.y, b0.z, b0.w, b1.x, b1.y, b1.z, b1.w};
#pragma unroll
            for (int i = 0; i < 8; i++)
#pragma unroll
                for (int j = 0; j < 8; j++) acc[i][j] += a[i] * b[j];
        }
        __syncthreads();
    }

    float* Cb = C + (size_t)(brow * 128 + tr * 8) * N + bcol * 128 + tc * 8;
#pragma unroll
    for (int i = 0; i < 8; i++) {
        *(float4*)&Cb[(size_t)i * N]     = make_float4(acc[i][0], acc[i][1], acc[i][2], acc[i][3]);
        *(float4*)&Cb[(size_t)i * N + 4] = make_float4(acc[i][4], acc[i][5], acc[i][6], acc[i][7]);
    }
}

// ---------------------------------------------------------------------------
// Flash attention (causal), fp32. One block per (b, h, q-tile of 64 rows).
// 256 threads. Thread (rg = tid/16, cg = tid%16) owns:
//   rows  rg*4 + ri          (ri in 0..3)
//   cols  cg + 16*ci         (ci in 0..3)  for scores/P
//   dims  cg + 16*di         (di in 0..3)  for the O accumulator
// Smem tiles are 64x64 fp32 with XOR swizzles chosen so all hot-loop
// LDS are conflict-free. P aliases the K tile buffer.
// ---------------------------------------------------------------------------
__global__ __launch_bounds__(256) void attn_flash64(const float* __restrict__ Q,
                                                    const float* __restrict__ K,
                                                    const float* __restrict__ V,
                                                    float* __restrict__ O) {
    __shared__ float Qt[64 * 64];  // Qt[d*64 + ((r + d) & 63)]
    __shared__ float KP[64 * 64];  // Kt[d*64 + ((c + d) & 63)]   then
                                   // Ps[r*64 + ((j + 4r) & 63)]
    __shared__ float Vs[64 * 64];  // Vs[j*64 + d]

    const int tid = threadIdx.x;
    const int qt  = blockIdx.x;              // q tile (0..31)
    const int bh  = blockIdx.y;              // 0..31
    const int b   = bh >> 4;
    const int h   = bh & 15;

    const float* Qb = Q + (size_t)(b * Sv) * Ev + h * Dv;
    const float* Kb = K + (size_t)(b * Sv) * Ev + h * Dv;
    const float* Vb = V + (size_t)(b * Sv) * Ev + h * Dv;

    const int rg = tid >> 4;   // 0..15
    const int cg = tid & 15;   // 0..15

    // Load Q tile (coalesced gmem, conflict-free swizzled smem store)
    for (int i = tid; i < 64 * 64; i += 256) {
        int d = i & 63, r = i >> 6;
        Qt[d * 64 + ((r + d) & 63)] = Qb[(size_t)(qt * 64 + r) * Ev + d];
    }

    float m[4], l[4], o[4][4];
#pragma unroll
    for (int ri = 0; ri < 4; ri++) {
        m[ri] = -1e30f;
        l[ri] = 0.0f;
#pragma unroll
        for (int di = 0; di < 4; di++) o[ri][di] = 0.0f;
    }
    const float scale = 0.125f;  // 1/sqrt(64)

    for (int kt = 0; kt <= qt; kt++) {
        __syncthreads();  // previous-iter KP/Vs readers done (also covers Qt load)
        for (int i = tid; i < 64 * 64; i += 256) {
            int d = i & 63, c = i >> 6;
            KP[d * 64 + ((c + d) & 63)] = Kb[(size_t)(kt * 64 + c) * Ev + d];
            Vs[c * 64 + d]              = Vb[(size_t)(kt * 64 + c) * Ev + d];
        }
        __syncthreads();

        // ---- scores: s[ri][ci] = q_row . k_col ----
        float s[4][4];
#pragma unroll
        for (int ri = 0; ri < 4; ri++)
#pragma unroll
            for (int ci = 0; ci < 4; ci++) s[ri][ci] = 0.0f;

        for (int d = 0; d < 64; d++) {
            float qv[4], kv[4];
#pragma unroll
            for (int ri = 0; ri < 4; ri++)
                qv[ri] = Qt[d * 64 + ((rg * 4 + ri + d) & 63)];
#pragma unroll
            for (int ci = 0; ci < 4; ci++)
                kv[ci] = KP[d * 64 + ((cg + 16 * ci + d) & 63)];
#pragma unroll
            for (int ri = 0; ri < 4; ri++)
#pragma unroll
                for (int ci = 0; ci < 4; ci++) s[ri][ci] += qv[ri] * kv[ci];
        }

        // scale + causal mask (only diagonal tile needs masking)
#pragma unroll
        for (int ri = 0; ri < 4; ri++)
#pragma unroll
            for (int ci = 0; ci < 4; ci++) {
                s[ri][ci] *= scale;
                if (kt == qt) {
                    int qrow = qt * 64 + rg * 4 + ri;
                    int kcol = kt * 64 + cg + 16 * ci;
                    if (kcol > qrow) s[ri][ci] = -1e30f;
                }
            }

        // ---- online softmax (row stats across the 16 lanes sharing rg) ----
        float p[4][4];
#pragma unroll
        for (int ri = 0; ri < 4; ri++) {
            float tm = fmaxf(fmaxf(s[ri][0], s[ri][1]), fmaxf(s[ri][2], s[ri][3]));
#pragma unroll
            for (int off = 1; off < 16; off <<= 1)
                tm = fmaxf(tm, __shfl_xor_sync(0xffffffffu, tm, off));
            float mn = fmaxf(m[ri], tm);
            float corr = __expf(m[ri] - mn);
            float rs = 0.0f;
#pragma unroll
            for (int ci = 0; ci < 4; ci++) {
                p[ri][ci] = __expf(s[ri][ci] - mn);
                rs += p[ri][ci];
            }
#pragma unroll
            for (int off = 1; off < 16; off <<= 1)
                rs += __shfl_xor_sync(0xffffffffu, rs, off);
            l[ri] = l[ri] * corr + rs;
            m[ri] = mn;
#pragma unroll
            for (int di = 0; di < 4; di++) o[ri][di] *= corr;
        }

        __syncthreads();  // all done reading Kt — safe to overwrite as Ps
#pragma unroll
        for (int ri = 0; ri < 4; ri++) {
            int row = rg * 4 + ri;
#pragma unroll
            for (int ci = 0; ci < 4; ci++) {
                int col = cg + 16 * ci;
                KP[row * 64 + ((col + 4 * row) & 63)] = p[ri][ci];
            }
        }
        __syncthreads();

        // ---- O += P @ V ----
        for (int j = 0; j < 64; j++) {
            float pv[4], vv[4];
#pragma unroll
            for (int ri = 0; ri < 4; ri++) {
                int row = rg * 4 + ri;
                pv[ri] = KP[row * 64 + ((j + 4 * row) & 63)];
            }
#pragma unroll
            for (int di = 0; di < 4; di++)
                vv[di] = Vs[j * 64 + cg + 16 * di];
#pragma unroll
            for (int ri = 0; ri < 4; ri++)
#pragma unroll
                for (int di = 0; di < 4; di++) o[ri][di] += pv[ri] * vv[di];
        }
    }

    // normalize + write
#pragma unroll
    for (int ri = 0; ri < 4; ri++) {
        float inv = 1.0f / l[ri];
        int row = qt * 64 + rg * 4 + ri;
#pragma unroll
        for (int di = 0; di < 4; di++) {
            int d = cg + 16 * di;
            O[(size_t)(b * Sv + row) * Ev + h * Dv + d] = o[ri][di] * inv;
        }
    }
}

// ---------------------------------------------------------------------------
// Launch
// ---------------------------------------------------------------------------
extern "C" void kernel_launch(void* const* d_in, const int* in_sizes, int n_in,
                              void* d_out, int out_size) {
    const float* x  = (const float*)d_in[0];
    const float* Wq = (const float*)d_in[1];
    const float* Wk = (const float*)d_in[2];
    const float* Wv = (const float*)d_in[3];
    const float* Wo = (const float*)d_in[4];
    float* out = (float*)d_out;

    float *Qp, *Kp, *Vp, *AOp;
    cudaGetSymbolAddress((void**)&Qp,  g_Q);
    cudaGetSymbolAddress((void**)&Kp,  g_K);
    cudaGetSymbolAddress((void**)&Vp,  g_V);
    cudaGetSymbolAddress((void**)&AOp, g_AO);

    dim3 gemmGrid(Ev / 128, MTOK / 128);   // (8, 32)
    sgemm128<<<gemmGrid, 256>>>(x, Wq, Qp, MTOK, Ev, Ev);
    sgemm128<<<gemmGrid, 256>>>(x, Wk, Kp, MTOK, Ev, Ev);
    sgemm128<<<gemmGrid, 256>>>(x, Wv, Vp, MTOK, Ev, Ev);

    dim3 attnGrid(Sv / 64, Bv * Hv);       // (32, 32)
    attn_flash64<<<attnGrid, 256>>>(Qp, Kp, Vp, AOp);

    sgemm128<<<gemmGrid, 256>>>(AOp, Wo, out, MTOK, Ev, Ev);
}

// round 3
// speedup vs baseline: 1.3504x; 1.3504x over previous
#include <cuda_runtime.h>
#include <cuda_bf16.h>
#include <cstdint>

// Problem constants
#define Bv   2
#define Sv   2048
#define Hv   16
#define Dv   64
#define Ev   1024
#define MTOK (Bv * Sv)   // 4096 tokens

// ---------------------------------------------------------------------------
// Scratch (device globals — no allocation allowed)
// ---------------------------------------------------------------------------
__device__ float g_Q [MTOK * Ev];
__device__ float g_K [MTOK * Ev];
__device__ float g_V [MTOK * Ev];
__device__ float g_AO[MTOK * Ev];
__device__ __nv_bfloat16 g_xhi[MTOK * Ev];
__device__ __nv_bfloat16 g_xlo[MTOK * Ev];
__device__ __nv_bfloat16 g_ahi[MTOK * Ev];
__device__ __nv_bfloat16 g_alo[MTOK * Ev];
__device__ __nv_bfloat16 g_wthi[4][Ev * Ev];   // W^T bf16 hi  [N,K]
__device__ __nv_bfloat16 g_wtlo[4][Ev * Ev];   // W^T bf16 lo  [N,K]

// ---------------------------------------------------------------------------
// PTX helpers (all baseline sm_80+ features — no arch-specific 'a' required)
// ---------------------------------------------------------------------------
__device__ __forceinline__ uint32_t smem_to_u32(const void* p) {
    uint32_t a;
    asm("{ .reg .u64 t; cvta.to.shared.u64 t, %1; cvt.u32.u64 %0, t; }"
        : "=r"(a) : "l"(p));
    return a;
}

__device__ __forceinline__ void cp_async16(uint32_t smem, const void* gmem) {
    asm volatile("cp.async.cg.shared.global [%0], [%1], 16;"
                 :: "r"(smem), "l"(gmem));
}
#define CP_COMMIT() asm volatile("cp.async.commit_group;" ::: "memory")
#define CP_WAIT1()  asm volatile("cp.async.wait_group 1;"  ::: "memory")

__device__ __forceinline__ void ldsm_x4(uint32_t* r, uint32_t addr) {
    asm volatile("ldmatrix.sync.aligned.m8n8.x4.shared.b16 {%0,%1,%2,%3}, [%4];"
                 : "=r"(r[0]), "=r"(r[1]), "=r"(r[2]), "=r"(r[3]) : "r"(addr));
}

__device__ __forceinline__ void mma16816(float* d, const uint32_t* a,
                                         uint32_t b0, uint32_t b1) {
    asm volatile(
        "mma.sync.aligned.m16n8k16.row.col.f32.bf16.bf16.f32 "
        "{%0,%1,%2,%3}, {%4,%5,%6,%7}, {%8,%9}, {%0,%1,%2,%3};"
        : "+f"(d[0]), "+f"(d[1]), "+f"(d[2]), "+f"(d[3])
        : "r"(a[0]), "r"(a[1]), "r"(a[2]), "r"(a[3]), "r"(b0), "r"(b1));
}

// ---------------------------------------------------------------------------
// Elementwise fp32 -> bf16 hi/lo split
// ---------------------------------------------------------------------------
__global__ __launch_bounds__(256) void split_hi_lo(const float* __restrict__ in,
                                                   __nv_bfloat16* __restrict__ hi,
                                                   __nv_bfloat16* __restrict__ lo,
                                                   int n) {
    int i = blockIdx.x * 256 + threadIdx.x;
    if (i < n) {
        float v = in[i];
        __nv_bfloat16 h = __float2bfloat16(v);
        hi[i] = h;
        lo[i] = __float2bfloat16(v - __bfloat162float(h));
    }
}

// ---------------------------------------------------------------------------
// Transpose + split: W [K,N] fp32 -> Wt hi/lo [N,K] bf16
// ---------------------------------------------------------------------------
__global__ __launch_bounds__(256) void transpose_split(const float* __restrict__ W,
                                                       __nv_bfloat16* __restrict__ Thi,
                                                       __nv_bfloat16* __restrict__ Tlo) {
    __shared__ float t[32][33];
    int n0 = blockIdx.x * 32, k0 = blockIdx.y * 32;
    int tx = threadIdx.x, ty = threadIdx.y;
    for (int i = ty; i < 32; i += 8)
        t[i][tx] = W[(size_t)(k0 + i) * Ev + n0 + tx];
    __syncthreads();
    for (int i = ty; i < 32; i += 8) {
        float v = t[tx][i];
        __nv_bfloat16 h = __float2bfloat16(v);
        size_t idx = (size_t)(n0 + i) * Ev + k0 + tx;
        Thi[idx] = h;
        Tlo[idx] = __float2bfloat16(v - __bfloat162float(h));
    }
}

// ---------------------------------------------------------------------------
// HMMA GEMM: C[M,N] = A[M,K] @ B^T, A row-major [M,K], Bt row-major [N,K].
// bf16x3 split. 128x128 CTA tile, BK=32, 3-stage cp.async pipeline, 8 warps
// in 2(M) x 4(N), warp tile 64x32, mma.sync.m16n8k16.
//
// Smem tile layout (per matrix): 128 rows x 32 bf16 = 64B/row, 4 16B chunks;
// chunk swizzle: ch ^= (row>>1)&3  -> conflict-free cp.async stores and
// ldmatrix reads.
// ---------------------------------------------------------------------------
#define BM 128
#define BN 128
#define BK 32
#define STAGES 3
#define TILE_B  8192u          // 128*32*2
#define STAGE_B (4u * TILE_B)  // Ahi, Alo, Bhi, Blo
#define GEMM_SMEM (STAGES * STAGE_B)   // 96 KB
#define NCHUNK (Ev / BK)       // 32

__global__ __launch_bounds__(256, 1) void gemm_hmma_bf16x3(
    const __nv_bfloat16* __restrict__ Ahi, const __nv_bfloat16* __restrict__ Alo,
    const __nv_bfloat16* __restrict__ Bhi, const __nv_bfloat16* __restrict__ Blo,
    float* __restrict__ C) {
    extern __shared__ char smc[];
    const uint32_t sbase = smem_to_u32(smc);
    const int tid  = threadIdx.x;
    const int lane = tid & 31;
    const int wid  = tid >> 5;
    const int warp_m = wid & 1;      // 0..1
    const int warp_n = wid >> 1;     // 0..3
    const int m0 = blockIdx.y * BM;
    const int n0 = blockIdx.x * BN;
    const int K = Ev, N = Ev;

    // ---- async load of one K-chunk into stage s ----
    auto load_stage = [&](int kc, int s) {
        uint32_t st = sbase + (uint32_t)s * STAGE_B;
#pragma unroll
        for (int half = 0; half < 2; half++) {
            int q   = tid + half * 256;      // 0..511
            int row = q >> 2;                // 0..127
            int ch  = q & 3;
            uint32_t sw = (uint32_t)(row * 64 + ((ch ^ ((row >> 1) & 3)) * 16));
            size_t ga = (size_t)(m0 + row) * K + kc * BK + ch * 8;
            size_t gb = (size_t)(n0 + row) * K + kc * BK + ch * 8;
            cp_async16(st + 0 * TILE_B + sw, Ahi + ga);
            cp_async16(st + 1 * TILE_B + sw, Alo + ga);
            cp_async16(st + 2 * TILE_B + sw, Bhi + gb);
            cp_async16(st + 3 * TILE_B + sw, Blo + gb);
        }
    };

    float acc[4][4][4];
#pragma unroll
    for (int mt = 0; mt < 4; mt++)
#pragma unroll
        for (int nt = 0; nt < 4; nt++)
#pragma unroll
            for (int e = 0; e < 4; e++) acc[mt][nt][e] = 0.0f;

    load_stage(0, 0); CP_COMMIT();
    load_stage(1, 1); CP_COMMIT();

    const int sub = lane >> 3;     // 0..3 (ldmatrix 8x8 submatrix id)
    const int r8  = lane & 7;

    for (int c = 0; c < NCHUNK; c++) {
        CP_WAIT1();
        __syncthreads();
        uint32_t st = sbase + (uint32_t)(c % STAGES) * STAGE_B;

#pragma unroll
        for (int ks = 0; ks < 2; ks++) {
            const int ch = ks * 2 + (sub >> 1);
            uint32_t ahi[4][4], alo[4][4];
#pragma unroll
            for (int mt = 0; mt < 4; mt++) {
                int row = warp_m * 64 + mt * 16 + (sub & 1) * 8 + r8;
                uint32_t addr = st + (uint32_t)(row * 64 + ((ch ^ ((row >> 1) & 3)) * 16));
                ldsm_x4(ahi[mt], addr);
                ldsm_x4(alo[mt], addr + TILE_B);
            }
            uint32_t bhi[2][4], blo[2][4];
#pragma unroll
            for (int np = 0; np < 2; np++) {
                int row = warp_n * 32 + np * 16 + (sub & 1) * 8 + r8;
                uint32_t addr = st + 2 * TILE_B +
                                (uint32_t)(row * 64 + ((ch ^ ((row >> 1) & 3)) * 16));
                ldsm_x4(bhi[np], addr);
                ldsm_x4(blo[np], addr + TILE_B);
            }
#pragma unroll
            for (int mt = 0; mt < 4; mt++)
#pragma unroll
                for (int nt = 0; nt < 4; nt++) {
                    uint32_t b0h = bhi[nt >> 1][nt & 1], b1h = bhi[nt >> 1][2 + (nt & 1)];
                    uint32_t b0l = blo[nt >> 1][nt & 1], b1l = blo[nt >> 1][2 + (nt & 1)];
                    mma16816(acc[mt][nt], ahi[mt], b0h, b1h);
                    mma16816(acc[mt][nt], ahi[mt], b0l, b1l);
                    mma16816(acc[mt][nt], alo[mt], b0h, b1h);
                }
        }
        __syncthreads();
        if (c + STAGES - 1 < NCHUNK) load_stage(c + STAGES - 1, (c + STAGES - 1) % STAGES);
        CP_COMMIT();   // always commit (possibly empty) to keep group accounting uniform
    }

    // ---- epilogue: fp32 accum -> C ----
    const int g   = lane >> 2;
    const int tig = lane & 3;
#pragma unroll
    for (int mt = 0; mt < 4; mt++) {
        int r0 = m0 + warp_m * 64 + mt * 16 + g;
#pragma unroll
        for (int nt = 0; nt < 4; nt++) {
            int col = n0 + warp_n * 32 + nt * 8 + tig * 2;
            *(float2*)&C[(size_t)r0 * N + col]       = make_float2(acc[mt][nt][0], acc[mt][nt][1]);
            *(float2*)&C[(size_t)(r0 + 8) * N + col] = make_float2(acc[mt][nt][2], acc[mt][nt][3]);
        }
    }
}

// ---------------------------------------------------------------------------
// Flash attention (causal), fp32 — unchanged from round 1.
// ---------------------------------------------------------------------------
__global__ __launch_bounds__(256) void attn_flash64(const float* __restrict__ Q,
                                                    const float* __restrict__ K,
                                                    const float* __restrict__ V,
                                                    float* __restrict__ O) {
    __shared__ float Qt[64 * 64];
    __shared__ float KP[64 * 64];
    __shared__ float Vs[64 * 64];

    const int tid = threadIdx.x;
    const int qt  = blockIdx.x;
    const int bh  = blockIdx.y;
    const int b   = bh >> 4;
    const int h   = bh & 15;

    const float* Qb = Q + (size_t)(b * Sv) * Ev + h * Dv;
    const float* Kb = K + (size_t)(b * Sv) * Ev + h * Dv;
    const float* Vb = V + (size_t)(b * Sv) * Ev + h * Dv;

    const int rg = tid >> 4;
    const int cg = tid & 15;

    for (int i = tid; i < 64 * 64; i += 256) {
        int d = i & 63, r = i >> 6;
        Qt[d * 64 + ((r + d) & 63)] = Qb[(size_t)(qt * 64 + r) * Ev + d];
    }

    float m[4], l[4], o[4][4];
#pragma unroll
    for (int ri = 0; ri < 4; ri++) {
        m[ri] = -1e30f;
        l[ri] = 0.0f;
#pragma unroll
        for (int di = 0; di < 4; di++) o[ri][di] = 0.0f;
    }
    const float scale = 0.125f;

    for (int kt = 0; kt <= qt; kt++) {
        __syncthreads();
        for (int i = tid; i < 64 * 64; i += 256) {
            int d = i & 63, c = i >> 6;
            KP[d * 64 + ((c + d) & 63)] = Kb[(size_t)(kt * 64 + c) * Ev + d];
            Vs[c * 64 + d]              = Vb[(size_t)(kt * 64 + c) * Ev + d];
        }
        __syncthreads();

        float s[4][4];
#pragma unroll
        for (int ri = 0; ri < 4; ri++)
#pragma unroll
            for (int ci = 0; ci < 4; ci++) s[ri][ci] = 0.0f;

        for (int d = 0; d < 64; d++) {
            float qv[4], kv[4];
#pragma unroll
            for (int ri = 0; ri < 4; ri++)
                qv[ri] = Qt[d * 64 + ((rg * 4 + ri + d) & 63)];
#pragma unroll
            for (int ci = 0; ci < 4; ci++)
                kv[ci] = KP[d * 64 + ((cg + 16 * ci + d) & 63)];
#pragma unroll
            for (int ri = 0; ri < 4; ri++)
#pragma unroll
                for (int ci = 0; ci < 4; ci++) s[ri][ci] += qv[ri] * kv[ci];
        }

#pragma unroll
        for (int ri = 0; ri < 4; ri++)
#pragma unroll
            for (int ci = 0; ci < 4; ci++) {
                s[ri][ci] *= scale;
                if (kt == qt) {
                    int qrow = qt * 64 + rg * 4 + ri;
                    int kcol = kt * 64 + cg + 16 * ci;
                    if (kcol > qrow) s[ri][ci] = -1e30f;
                }
            }

        float p[4][4];
#pragma unroll
        for (int ri = 0; ri < 4; ri++) {
            float tm = fmaxf(fmaxf(s[ri][0], s[ri][1]), fmaxf(s[ri][2], s[ri][3]));
#pragma unroll
            for (int off = 1; off < 16; off <<= 1)
                tm = fmaxf(tm, __shfl_xor_sync(0xffffffffu, tm, off));
            float mn = fmaxf(m[ri], tm);
            float corr = __expf(m[ri] - mn);
            float rs = 0.0f;
#pragma unroll
            for (int ci = 0; ci < 4; ci++) {
                p[ri][ci] = __expf(s[ri][ci] - mn);
                rs += p[ri][ci];
            }
#pragma unroll
            for (int off = 1; off < 16; off <<= 1)
                rs += __shfl_xor_sync(0xffffffffu, rs, off);
            l[ri] = l[ri] * corr + rs;
            m[ri] = mn;
#pragma unroll
            for (int di = 0; di < 4; di++) o[ri][di] *= corr;
        }

        __syncthreads();
#pragma unroll
        for (int ri = 0; ri < 4; ri++) {
            int row = rg * 4 + ri;
#pragma unroll
            for (int ci = 0; ci < 4; ci++) {
                int col = cg + 16 * ci;
                KP[row * 64 + ((col + 4 * row) & 63)] = p[ri][ci];
            }
        }
        __syncthreads();

        for (int j = 0; j < 64; j++) {
            float pv[4], vv[4];
#pragma unroll
            for (int ri = 0; ri < 4; ri++) {
                int row = rg * 4 + ri;
                pv[ri] = KP[row * 64 + ((j + 4 * row) & 63)];
            }
#pragma unroll
            for (int di = 0; di < 4; di++)
                vv[di] = Vs[j * 64 + cg + 16 * di];
#pragma unroll
            for (int ri = 0; ri < 4; ri++)
#pragma unroll
                for (int di = 0; di < 4; di++) o[ri][di] += pv[ri] * vv[di];
        }
    }

#pragma unroll
    for (int ri = 0; ri < 4; ri++) {
        float inv = 1.0f / l[ri];
        int row = qt * 64 + rg * 4 + ri;
#pragma unroll
        for (int di = 0; di < 4; di++) {
            int d = cg + 16 * di;
            O[(size_t)(b * Sv + row) * Ev + h * Dv + d] = o[ri][di] * inv;
        }
    }
}

// ---------------------------------------------------------------------------
// Launch
// ---------------------------------------------------------------------------
extern "C" void kernel_launch(void* const* d_in, const int* in_sizes, int n_in,
                              void* d_out, int out_size) {
    const float* x  = (const float*)d_in[0];
    const float* Wq = (const float*)d_in[1];
    const float* Wk = (const float*)d_in[2];
    const float* Wv = (const float*)d_in[3];
    const float* Wo = (const float*)d_in[4];
    float* out = (float*)d_out;

    float *Qp, *Kp, *Vp, *AOp;
    __nv_bfloat16 *xhi, *xlo, *ahi, *alo, *wthi, *wtlo;
    cudaGetSymbolAddress((void**)&Qp,   g_Q);
    cudaGetSymbolAddress((void**)&Kp,   g_K);
    cudaGetSymbolAddress((void**)&Vp,   g_V);
    cudaGetSymbolAddress((void**)&AOp,  g_AO);
    cudaGetSymbolAddress((void**)&xhi,  g_xhi);
    cudaGetSymbolAddress((void**)&xlo,  g_xlo);
    cudaGetSymbolAddress((void**)&ahi,  g_ahi);
    cudaGetSymbolAddress((void**)&alo,  g_alo);
    cudaGetSymbolAddress((void**)&wthi, g_wthi);
    cudaGetSymbolAddress((void**)&wtlo, g_wtlo);

    static bool attr_set = false;
    if (!attr_set) {
        cudaFuncSetAttribute(gemm_hmma_bf16x3,
                             cudaFuncAttributeMaxDynamicSharedMemorySize, GEMM_SMEM);
        attr_set = true;
    }

    const int nElem = MTOK * Ev;
    const float* W[4] = {Wq, Wk, Wv, Wo};

    // 1. split x into bf16 hi/lo
    split_hi_lo<<<nElem / 256, 256>>>(x, xhi, xlo, nElem);

    // 2. transpose + split weights
    dim3 tGrid(Ev / 32, Ev / 32), tBlk(32, 8);
    for (int w = 0; w < 4; w++)
        transpose_split<<<tGrid, tBlk>>>(W[w], wthi + (size_t)w * Ev * Ev,
                                         wtlo + (size_t)w * Ev * Ev);

    // 3. Q/K/V projections on HMMA tensor cores
    dim3 gGrid(Ev / BN, MTOK / BM);   // (8, 32)
    float* QKV[3] = {Qp, Kp, Vp};
    for (int w = 0; w < 3; w++)
        gemm_hmma_bf16x3<<<gGrid, 256, GEMM_SMEM>>>(
            xhi, xlo, wthi + (size_t)w * Ev * Ev, wtlo + (size_t)w * Ev * Ev, QKV[w]);

    // 4. attention
    dim3 attnGrid(Sv / 64, Bv * Hv);
    attn_flash64<<<attnGrid, 256>>>(Qp, Kp, Vp, AOp);

    // 5. output projection
    split_hi_lo<<<nElem / 256, 256>>>(AOp, ahi, alo, nElem);
    gemm_hmma_bf16x3<<<gGrid, 256, GEMM_SMEM>>>(
        ahi, alo, wthi + (size_t)3 * Ev * Ev, wtlo + (size_t)3 * Ev * Ev, out);
}

// round 4
// speedup vs baseline: 3.7586x; 2.7834x over previous
#include <cuda_runtime.h>
#include <cuda_bf16.h>
#include <cstdint>

// Problem constants
#define Bv   2
#define Sv   2048
#define Hv   16
#define Dv   64
#define Ev   1024
#define MTOK (Bv * Sv)   // 4096 tokens

// ---------------------------------------------------------------------------
// Scratch (device globals — no allocation allowed)
// ---------------------------------------------------------------------------
__device__ __nv_bfloat16 g_qhi[MTOK * Ev], g_qlo[MTOK * Ev];
__device__ __nv_bfloat16 g_khi[MTOK * Ev], g_klo[MTOK * Ev];
__device__ __nv_bfloat16 g_vhi[MTOK * Ev], g_vlo[MTOK * Ev];
__device__ __nv_bfloat16 g_aohi[MTOK * Ev], g_aolo[MTOK * Ev];
__device__ __nv_bfloat16 g_xhi[MTOK * Ev], g_xlo[MTOK * Ev];
__device__ __nv_bfloat16 g_wthi[4][Ev * Ev];   // W^T bf16 hi  [N,K]
__device__ __nv_bfloat16 g_wtlo[4][Ev * Ev];   // W^T bf16 lo  [N,K]

// ---------------------------------------------------------------------------
// PTX helpers (baseline sm_80+ — compile without arch 'a' suffix)
// ---------------------------------------------------------------------------
__device__ __forceinline__ uint32_t smem_to_u32(const void* p) {
    uint32_t a;
    asm("{ .reg .u64 t; cvta.to.shared.u64 t, %1; cvt.u32.u64 %0, t; }"
        : "=r"(a) : "l"(p));
    return a;
}
__device__ __forceinline__ void cp_async16(uint32_t smem, const void* gmem) {
    asm volatile("cp.async.cg.shared.global [%0], [%1], 16;"
                 :: "r"(smem), "l"(gmem));
}
#define CP_COMMIT() asm volatile("cp.async.commit_group;" ::: "memory")
#define CP_WAIT1()  asm volatile("cp.async.wait_group 1;"  ::: "memory")

__device__ __forceinline__ void ldsm_x4(uint32_t* r, uint32_t addr) {
    asm volatile("ldmatrix.sync.aligned.m8n8.x4.shared.b16 {%0,%1,%2,%3}, [%4];"
                 : "=r"(r[0]), "=r"(r[1]), "=r"(r[2]), "=r"(r[3]) : "r"(addr));
}
__device__ __forceinline__ void ldsm_x4_t(uint32_t* r, uint32_t addr) {
    asm volatile("ldmatrix.sync.aligned.m8n8.x4.trans.shared.b16 {%0,%1,%2,%3}, [%4];"
                 : "=r"(r[0]), "=r"(r[1]), "=r"(r[2]), "=r"(r[3]) : "r"(addr));
}
__device__ __forceinline__ void mma16816(float* d, const uint32_t* a,
                                         uint32_t b0, uint32_t b1) {
    asm volatile(
        "mma.sync.aligned.m16n8k16.row.col.f32.bf16.bf16.f32 "
        "{%0,%1,%2,%3}, {%4,%5,%6,%7}, {%8,%9}, {%0,%1,%2,%3};"
        : "+f"(d[0]), "+f"(d[1]), "+f"(d[2]), "+f"(d[3])
        : "r"(a[0]), "r"(a[1]), "r"(a[2]), "r"(a[3]), "r"(b0), "r"(b1));
}
// pack the top-16-bits (bf16 truncation) of two floats: {lo:a_hi16, hi:b_hi16}
__device__ __forceinline__ uint32_t pack_hi_trunc(float a, float b) {
    uint32_t r;
    asm("prmt.b32 %0, %1, %2, 0x7632;" : "=r"(r)
        : "r"(__float_as_uint(a)), "r"(__float_as_uint(b)));
    return r;
}
__device__ __forceinline__ float trunc_hi(float a) {
    return __uint_as_float(__float_as_uint(a) & 0xFFFF0000u);
}
// round-to-nearest bf16x2 pack: {lo:cvt(a), hi:cvt(b)}
__device__ __forceinline__ uint32_t pack_bf16(float a, float b) {
    uint32_t r;
    asm("cvt.rn.bf16x2.f32 %0, %1, %2;" : "=r"(r) : "f"(b), "f"(a));
    return r;
}
__device__ __forceinline__ float ex2(float x) {
    float r; asm("ex2.approx.f32 %0, %1;" : "=f"(r) : "f"(x)); return r;
}

// ---------------------------------------------------------------------------
// Elementwise fp32 -> bf16 hi/lo split (round-nearest hi)
// ---------------------------------------------------------------------------
__global__ __launch_bounds__(256) void split_hi_lo(const float* __restrict__ in,
                                                   __nv_bfloat16* __restrict__ hi,
                                                   __nv_bfloat16* __restrict__ lo,
                                                   int n) {
    int i = blockIdx.x * 256 + threadIdx.x;
    if (i < n) {
        float v = in[i];
        __nv_bfloat16 h = __float2bfloat16(v);
        hi[i] = h;
        lo[i] = __float2bfloat16(v - __bfloat162float(h));
    }
}

// ---------------------------------------------------------------------------
// Transpose + split: W [K,N] fp32 -> Wt hi/lo [N,K] bf16
// ---------------------------------------------------------------------------
__global__ __launch_bounds__(256) void transpose_split(const float* __restrict__ W,
                                                       __nv_bfloat16* __restrict__ Thi,
                                                       __nv_bfloat16* __restrict__ Tlo) {
    __shared__ float t[32][33];
    int n0 = blockIdx.x * 32, k0 = blockIdx.y * 32;
    int tx = threadIdx.x, ty = threadIdx.y;
    for (int i = ty; i < 32; i += 8)
        t[i][tx] = W[(size_t)(k0 + i) * Ev + n0 + tx];
    __syncthreads();
    for (int i = ty; i < 32; i += 8) {
        float v = t[tx][i];
        __nv_bfloat16 h = __float2bfloat16(v);
        size_t idx = (size_t)(n0 + i) * Ev + k0 + tx;
        Thi[idx] = h;
        Tlo[idx] = __float2bfloat16(v - __bfloat162float(h));
    }
}

// ---------------------------------------------------------------------------
// HMMA GEMM (as R3): C = A @ B^T, bf16x3 split, 128x128x32, 3-stage cp.async.
// SPLIT_OUT=false: write fp32 C.  SPLIT_OUT=true: write bf16 hi/lo (trunc split).
// ---------------------------------------------------------------------------
#define BM 128
#define BN 128
#define BK 32
#define STAGES 3
#define TILE_B  8192u
#define STAGE_B (4u * TILE_B)
#define GEMM_SMEM (STAGES * STAGE_B)   // 96 KB
#define NCHUNK (Ev / BK)               // 32

template <bool SPLIT_OUT>
__global__ __launch_bounds__(256, 1) void gemm_hmma_bf16x3(
    const __nv_bfloat16* __restrict__ Ahi, const __nv_bfloat16* __restrict__ Alo,
    const __nv_bfloat16* __restrict__ Bhi, const __nv_bfloat16* __restrict__ Blo,
    float* __restrict__ C,
    __nv_bfloat16* __restrict__ Chi, __nv_bfloat16* __restrict__ Clo) {
    extern __shared__ char smc[];
    const uint32_t sbase = smem_to_u32(smc);
    const int tid  = threadIdx.x;
    const int lane = tid & 31;
    const int wid  = tid >> 5;
    const int warp_m = wid & 1;
    const int warp_n = wid >> 1;
    const int m0 = blockIdx.y * BM;
    const int n0 = blockIdx.x * BN;
    const int K = Ev, N = Ev;

    auto load_stage = [&](int kc, int s) {
        uint32_t st = sbase + (uint32_t)s * STAGE_B;
#pragma unroll
        for (int half = 0; half < 2; half++) {
            int q   = tid + half * 256;
            int row = q >> 2;
            int ch  = q & 3;
            uint32_t sw = (uint32_t)(row * 64 + ((ch ^ ((row >> 1) & 3)) * 16));
            size_t ga = (size_t)(m0 + row) * K + kc * BK + ch * 8;
            size_t gb = (size_t)(n0 + row) * K + kc * BK + ch * 8;
            cp_async16(st + 0 * TILE_B + sw, Ahi + ga);
            cp_async16(st + 1 * TILE_B + sw, Alo + ga);
            cp_async16(st + 2 * TILE_B + sw, Bhi + gb);
            cp_async16(st + 3 * TILE_B + sw, Blo + gb);
        }
    };

    float acc[4][4][4];
#pragma unroll
    for (int mt = 0; mt < 4; mt++)
#pragma unroll
        for (int nt = 0; nt < 4; nt++)
#pragma unroll
            for (int e = 0; e < 4; e++) acc[mt][nt][e] = 0.0f;

    load_stage(0, 0); CP_COMMIT();
    load_stage(1, 1); CP_COMMIT();

    const int sub = lane >> 3;
    const int r8  = lane & 7;

    for (int c = 0; c < NCHUNK; c++) {
        CP_WAIT1();
        __syncthreads();
        uint32_t st = sbase + (uint32_t)(c % STAGES) * STAGE_B;

#pragma unroll
        for (int ks = 0; ks < 2; ks++) {
            const int ch = ks * 2 + (sub >> 1);
            uint32_t ahi[4][4], alo[4][4];
#pragma unroll
            for (int mt = 0; mt < 4; mt++) {
                int row = warp_m * 64 + mt * 16 + (sub & 1) * 8 + r8;
                uint32_t addr = st + (uint32_t)(row * 64 + ((ch ^ ((row >> 1) & 3)) * 16));
                ldsm_x4(ahi[mt], addr);
                ldsm_x4(alo[mt], addr + TILE_B);
            }
            uint32_t bhi[2][4], blo[2][4];
#pragma unroll
            for (int np = 0; np < 2; np++) {
                int row = warp_n * 32 + np * 16 + (sub & 1) * 8 + r8;
                uint32_t addr = st + 2 * TILE_B +
                                (uint32_t)(row * 64 + ((ch ^ ((row >> 1) & 3)) * 16));
                ldsm_x4(bhi[np], addr);
                ldsm_x4(blo[np], addr + TILE_B);
            }
#pragma unroll
            for (int mt = 0; mt < 4; mt++)
#pragma unroll
                for (int nt = 0; nt < 4; nt++) {
                    uint32_t b0h = bhi[nt >> 1][nt & 1], b1h = bhi[nt >> 1][2 + (nt & 1)];
                    uint32_t b0l = blo[nt >> 1][nt & 1], b1l = blo[nt >> 1][2 + (nt & 1)];
                    mma16816(acc[mt][nt], ahi[mt], b0h, b1h);
                    mma16816(acc[mt][nt], ahi[mt], b0l, b1l);
                    mma16816(acc[mt][nt], alo[mt], b0h, b1h);
                }
        }
        __syncthreads();
        if (c + STAGES - 1 < NCHUNK) load_stage(c + STAGES - 1, (c + STAGES - 1) % STAGES);
        CP_COMMIT();
    }

    const int g   = lane >> 2;
    const int tig = lane & 3;
#pragma unroll
    for (int mt = 0; mt < 4; mt++) {
        int r0 = m0 + warp_m * 64 + mt * 16 + g;
#pragma unroll
        for (int nt = 0; nt < 4; nt++) {
            int col = n0 + warp_n * 32 + nt * 8 + tig * 2;
            float* a = acc[mt][nt];
            if (SPLIT_OUT) {
                *(uint32_t*)&Chi[(size_t)r0 * N + col] = pack_hi_trunc(a[0], a[1]);
                *(uint32_t*)&Clo[(size_t)r0 * N + col] =
                    pack_bf16(a[0] - trunc_hi(a[0]), a[1] - trunc_hi(a[1]));
                *(uint32_t*)&Chi[(size_t)(r0 + 8) * N + col] = pack_hi_trunc(a[2], a[3]);
                *(uint32_t*)&Clo[(size_t)(r0 + 8) * N + col] =
                    pack_bf16(a[2] - trunc_hi(a[2]), a[3] - trunc_hi(a[3]));
            } else {
                *(float2*)&C[(size_t)r0 * N + col]       = make_float2(a[0], a[1]);
                *(float2*)&C[(size_t)(r0 + 8) * N + col] = make_float2(a[2], a[3]);
            }
        }
    }
}

// ---------------------------------------------------------------------------
// HMMA flash attention (causal). CTA: 128 q-rows x one head. 8 warps, each
// owns 16 q-rows. KV tiles of 64, double-buffered cp.async.
// S = Qhi*Khi + Qhi*Klo + Qlo*Khi ; P trunc-split ; O += Phi*Vhi+Phi*Vlo+Plo*Vhi.
// Smem: Qhi(16K) Qlo(16K) | stage s: Khi Klo Vhi Vlo (8K each) x2 = 96KB.
// Tile rows are 128B (64 bf16), chunk swizzle ch ^= row&7.
// ---------------------------------------------------------------------------
#define ATT_SMEM (32768 + 2 * 32768)

__global__ __launch_bounds__(256, 1) void attn_hmma(
    const __nv_bfloat16* __restrict__ Qhi, const __nv_bfloat16* __restrict__ Qlo,
    const __nv_bfloat16* __restrict__ Khi, const __nv_bfloat16* __restrict__ Klo,
    const __nv_bfloat16* __restrict__ Vhi, const __nv_bfloat16* __restrict__ Vlo,
    __nv_bfloat16* __restrict__ AOhi, __nv_bfloat16* __restrict__ AOlo) {
    extern __shared__ char smc[];
    const uint32_t sb = smem_to_u32(smc);
    const int tid = threadIdx.x, lane = tid & 31, wid = tid >> 5;
    const int qt = (int)gridDim.x - 1 - (int)blockIdx.x;  // heavy tiles first
    const int bh = blockIdx.y;
    const int b  = bh >> 4, h = bh & 15;
    const size_t base = (size_t)(b * Sv) * Ev + h * Dv;

    const int sub = lane >> 3, r8 = lane & 7, g = lane >> 2, tig = lane & 3;

    const uint32_t sQhi = sb, sQlo = sb + 16384;
    auto stage = [&](int s) { return sb + 32768 + (uint32_t)s * 32768; };
    auto sw = [](int row, int ch) {
        return (uint32_t)(row * 128 + ((ch ^ (row & 7)) * 16));
    };

    // Q tile loads (group 0, together with KV tile 0)
    {
        const __nv_bfloat16* q0 = Qhi + base + (size_t)(qt * 128) * Ev;
        const __nv_bfloat16* q1 = Qlo + base + (size_t)(qt * 128) * Ev;
        for (int i = tid; i < 1024; i += 256) {
            int row = i >> 3, ch = i & 7;
            size_t off = (size_t)row * Ev + ch * 8;
            cp_async16(sQhi + sw(row, ch), q0 + off);
            cp_async16(sQlo + sw(row, ch), q1 + off);
        }
    }
    auto loadKV = [&](int j, int s) {
        uint32_t st = stage(s);
        const __nv_bfloat16* kh = Khi + base + (size_t)(j * 64) * Ev;
        const __nv_bfloat16* kl = Klo + base + (size_t)(j * 64) * Ev;
        const __nv_bfloat16* vh = Vhi + base + (size_t)(j * 64) * Ev;
        const __nv_bfloat16* vl = Vlo + base + (size_t)(j * 64) * Ev;
#pragma unroll
        for (int rep = 0; rep < 2; rep++) {
            int i = tid + rep * 256;           // 0..511
            int row = i >> 3, ch = i & 7;
            size_t off = (size_t)row * Ev + ch * 8;
            uint32_t d = sw(row, ch);
            cp_async16(st + d,         kh + off);
            cp_async16(st + 8192 + d,  kl + off);
            cp_async16(st + 16384 + d, vh + off);
            cp_async16(st + 24576 + d, vl + off);
        }
    };
    loadKV(0, 0); CP_COMMIT();

    const int ntiles = 2 * qt + 2;
    const int wr0 = qt * 128 + wid * 16;       // warp's first global q-row
    const float Cc = 0.125f * 1.44269504f;     // scale * log2(e)

    float m0 = -1e30f, m1 = -1e30f, l0 = 0.f, l1 = 0.f;
    float o[8][4];
#pragma unroll
    for (int nt = 0; nt < 8; nt++)
#pragma unroll
        for (int e = 0; e < 4; e++) o[nt][e] = 0.f;
    uint32_t qh[4][4], ql[4][4];

    for (int j = 0; j < ntiles; j++) {
        __syncthreads();                       // all warps done with iter j-1
        if (j + 1 < ntiles) loadKV(j + 1, (j + 1) & 1);
        CP_COMMIT();
        CP_WAIT1();                            // tile j (and Q on j=0) resident
        __syncthreads();
        uint32_t st = stage(j & 1);

        if (j == 0) {
#pragma unroll
            for (int ks = 0; ks < 4; ks++) {
                int row = wid * 16 + (sub & 1) * 8 + r8;
                int ch  = ks * 2 + (sub >> 1);
                ldsm_x4(qh[ks], sQhi + sw(row, ch));
                ldsm_x4(ql[ks], sQlo + sw(row, ch));
            }
        }

        // ---- S = Q K^T (3-term split) ----
        float s[8][4];
#pragma unroll
        for (int nt = 0; nt < 8; nt++)
#pragma unroll
            for (int e = 0; e < 4; e++) s[nt][e] = 0.f;

#pragma unroll
        for (int ks = 0; ks < 4; ks++) {
            uint32_t kh4[4][4], kl4[4][4];
#pragma unroll
            for (int np = 0; np < 4; np++) {
                int row = np * 16 + (sub & 1) * 8 + r8;
                int ch  = ks * 2 + (sub >> 1);
                uint32_t a = st + sw(row, ch);
                ldsm_x4(kh4[np], a);
                ldsm_x4(kl4[np], a + 8192);
            }
#pragma unroll
            for (int nt = 0; nt < 8; nt++) {
                uint32_t b0h = kh4[nt >> 1][nt & 1], b1h = kh4[nt >> 1][2 + (nt & 1)];
                uint32_t b0l = kl4[nt >> 1][nt & 1], b1l = kl4[nt >> 1][2 + (nt & 1)];
                mma16816(s[nt], qh[ks], b0h, b1h);
                mma16816(s[nt], qh[ks], b0l, b1l);
                mma16816(s[nt], ql[ks], b0h, b1h);
            }
        }

        // ---- causal mask (only the two diagonal tiles need it) ----
        if (j >= 2 * qt) {
            int colb = j * 64;
            int row0 = wr0 + g, row1 = row0 + 8;
#pragma unroll
            for (int nt = 0; nt < 8; nt++) {
                int c0 = colb + nt * 8 + tig * 2;
                if (c0     > row0) s[nt][0] = -1e30f;
                if (c0 + 1 > row0) s[nt][1] = -1e30f;
                if (c0     > row1) s[nt][2] = -1e30f;
                if (c0 + 1 > row1) s[nt][3] = -1e30f;
            }
        }

        // ---- online softmax (2 rows per thread; quad-shuffle reduce) ----
        float mx0 = -1e30f, mx1 = -1e30f;
#pragma unroll
        for (int nt = 0; nt < 8; nt++) {
            mx0 = fmaxf(mx0, fmaxf(s[nt][0], s[nt][1]));
            mx1 = fmaxf(mx1, fmaxf(s[nt][2], s[nt][3]));
        }
        mx0 = fmaxf(mx0, __shfl_xor_sync(0xffffffffu, mx0, 1));
        mx0 = fmaxf(mx0, __shfl_xor_sync(0xffffffffu, mx0, 2));
        mx1 = fmaxf(mx1, __shfl_xor_sync(0xffffffffu, mx1, 1));
        mx1 = fmaxf(mx1, __shfl_xor_sync(0xffffffffu, mx1, 2));
        float nm0 = fmaxf(m0, mx0), nm1 = fmaxf(m1, mx1);
        float cr0 = ex2((m0 - nm0) * Cc), cr1 = ex2((m1 - nm1) * Cc);
        m0 = nm0; m1 = nm1;
        float rs0 = 0.f, rs1 = 0.f;
#pragma unroll
        for (int nt = 0; nt < 8; nt++) {
            s[nt][0] = ex2((s[nt][0] - m0) * Cc); rs0 += s[nt][0];
            s[nt][1] = ex2((s[nt][1] - m0) * Cc); rs0 += s[nt][1];
            s[nt][2] = ex2((s[nt][2] - m1) * Cc); rs1 += s[nt][2];
            s[nt][3] = ex2((s[nt][3] - m1) * Cc); rs1 += s[nt][3];
        }
        rs0 += __shfl_xor_sync(0xffffffffu, rs0, 1);
        rs0 += __shfl_xor_sync(0xffffffffu, rs0, 2);
        rs1 += __shfl_xor_sync(0xffffffffu, rs1, 1);
        rs1 += __shfl_xor_sync(0xffffffffu, rs1, 2);
        l0 = l0 * cr0 + rs0;
        l1 = l1 * cr1 + rs1;
#pragma unroll
        for (int nt = 0; nt < 8; nt++) {
            o[nt][0] *= cr0; o[nt][1] *= cr0;
            o[nt][2] *= cr1; o[nt][3] *= cr1;
        }

        // ---- P fragments (trunc split, built straight from acc layout) ----
        uint32_t ph[4][4], pl[4][4];
#pragma unroll
        for (int j2 = 0; j2 < 4; j2++) {
            float* e0 = s[2 * j2];
            float* e1 = s[2 * j2 + 1];
            ph[j2][0] = pack_hi_trunc(e0[0], e0[1]);
            ph[j2][1] = pack_hi_trunc(e0[2], e0[3]);
            ph[j2][2] = pack_hi_trunc(e1[0], e1[1]);
            ph[j2][3] = pack_hi_trunc(e1[2], e1[3]);
            pl[j2][0] = pack_bf16(e0[0] - trunc_hi(e0[0]), e0[1] - trunc_hi(e0[1]));
            pl[j2][1] = pack_bf16(e0[2] - trunc_hi(e0[2]), e0[3] - trunc_hi(e0[3]));
            pl[j2][2] = pack_bf16(e1[0] - trunc_hi(e1[0]), e1[1] - trunc_hi(e1[1]));
            pl[j2][3] = pack_bf16(e1[2] - trunc_hi(e1[2]), e1[3] - trunc_hi(e1[3]));
        }

        // ---- O += P V (V via ldmatrix.trans; 3-term split) ----
#pragma unroll
        for (int ks = 0; ks < 4; ks++) {        // kv k-steps
#pragma unroll
            for (int dv = 0; dv < 4; dv++) {    // d 16-col pairs
                int row = ks * 16 + (sub & 1) * 8 + r8;
                int ch  = dv * 2 + (sub >> 1);
                uint32_t a = st + sw(row, ch);
                uint32_t vh4[4], vl4[4];
                ldsm_x4_t(vh4, a + 16384);
                ldsm_x4_t(vl4, a + 24576);
                mma16816(o[2 * dv],     ph[ks], vh4[0], vh4[1]);
                mma16816(o[2 * dv],     ph[ks], vl4[0], vl4[1]);
                mma16816(o[2 * dv],     pl[ks], vh4[0], vh4[1]);
                mma16816(o[2 * dv + 1], ph[ks], vh4[2], vh4[3]);
                mma16816(o[2 * dv + 1], ph[ks], vl4[2], vl4[3]);
                mma16816(o[2 * dv + 1], pl[ks], vh4[2], vh4[3]);
            }
        }
    }

    // ---- normalize + write AO as bf16 hi/lo ----
    float i0 = 1.0f / l0, i1 = 1.0f / l1;
    int t0 = qt * 128 + wid * 16 + g, t1 = t0 + 8;
#pragma unroll
    for (int nt = 0; nt < 8; nt++) {
        int col = nt * 8 + tig * 2;
        float a0 = o[nt][0] * i0, a1 = o[nt][1] * i0;
        float a2 = o[nt][2] * i1, a3 = o[nt][3] * i1;
        *(uint32_t*)&AOhi[base + (size_t)t0 * Ev + col] = pack_hi_trunc(a0, a1);
        *(uint32_t*)&AOlo[base + (size_t)t0 * Ev + col] =
            pack_bf16(a0 - trunc_hi(a0), a1 - trunc_hi(a1));
        *(uint32_t*)&AOhi[base + (size_t)t1 * Ev + col] = pack_hi_trunc(a2, a3);
        *(uint32_t*)&AOlo[base + (size_t)t1 * Ev + col] =
            pack_bf16(a2 - trunc_hi(a2), a3 - trunc_hi(a3));
    }
}

// ---------------------------------------------------------------------------
// Launch
// ---------------------------------------------------------------------------
extern "C" void kernel_launch(void* const* d_in, const int* in_sizes, int n_in,
                              void* d_out, int out_size) {
    const float* x  = (const float*)d_in[0];
    const float* Wq = (const float*)d_in[1];
    const float* Wk = (const float*)d_in[2];
    const float* Wv = (const float*)d_in[3];
    const float* Wo = (const float*)d_in[4];
    float* out = (float*)d_out;

    __nv_bfloat16 *qhi, *qlo, *khi, *klo, *vhi, *vlo, *aohi, *aolo;
    __nv_bfloat16 *xhi, *xlo, *wthi, *wtlo;
    cudaGetSymbolAddress((void**)&qhi,  g_qhi);
    cudaGetSymbolAddress((void**)&qlo,  g_qlo);
    cudaGetSymbolAddress((void**)&khi,  g_khi);
    cudaGetSymbolAddress((void**)&klo,  g_klo);
    cudaGetSymbolAddress((void**)&vhi,  g_vhi);
    cudaGetSymbolAddress((void**)&vlo,  g_vlo);
    cudaGetSymbolAddress((void**)&aohi, g_aohi);
    cudaGetSymbolAddress((void**)&aolo, g_aolo);
    cudaGetSymbolAddress((void**)&xhi,  g_xhi);
    cudaGetSymbolAddress((void**)&xlo,  g_xlo);
    cudaGetSymbolAddress((void**)&wthi, g_wthi);
    cudaGetSymbolAddress((void**)&wtlo, g_wtlo);

    static bool attr_set = false;
    if (!attr_set) {
        cudaFuncSetAttribute(gemm_hmma_bf16x3<true>,
                             cudaFuncAttributeMaxDynamicSharedMemorySize, GEMM_SMEM);
        cudaFuncSetAttribute(gemm_hmma_bf16x3<false>,
                             cudaFuncAttributeMaxDynamicSharedMemorySize, GEMM_SMEM);
        cudaFuncSetAttribute(attn_hmma,
                             cudaFuncAttributeMaxDynamicSharedMemorySize, ATT_SMEM);
        attr_set = true;
    }

    const int nElem = MTOK * Ev;
    const float* W[4] = {Wq, Wk, Wv, Wo};

    // 1. split x into bf16 hi/lo
    split_hi_lo<<<nElem / 256, 256>>>(x, xhi, xlo, nElem);

    // 2. transpose + split weights
    dim3 tGrid(Ev / 32, Ev / 32), tBlk(32, 8);
    for (int w = 0; w < 4; w++)
        transpose_split<<<tGrid, tBlk>>>(W[w], wthi + (size_t)w * Ev * Ev,
                                         wtlo + (size_t)w * Ev * Ev);

    // 3. Q/K/V projections -> bf16 hi/lo directly
    dim3 gGrid(Ev / BN, MTOK / BM);
    __nv_bfloat16* outsHi[3] = {qhi, khi, vhi};
    __nv_bfloat16* outsLo[3] = {qlo, klo, vlo};
    for (int w = 0; w < 3; w++)
        gemm_hmma_bf16x3<true><<<gGrid, 256, GEMM_SMEM>>>(
            xhi, xlo, wthi + (size_t)w * Ev * Ev, wtlo + (size_t)w * Ev * Ev,
            nullptr, outsHi[w], outsLo[w]);

    // 4. HMMA flash attention -> AO bf16 hi/lo
    dim3 attnGrid(Sv / 128, Bv * Hv);   // (16, 32)
    attn_hmma<<<attnGrid, 256, ATT_SMEM>>>(qhi, qlo, khi, klo, vhi, vlo,
                                           aohi, aolo);

    // 5. output projection -> fp32 out
    gemm_hmma_bf16x3<false><<<gGrid, 256, GEMM_SMEM>>>(
        aohi, aolo, wthi + (size_t)3 * Ev * Ev, wtlo + (size_t)3 * Ev * Ev,
        out, nullptr, nullptr);
}

// round 5
// speedup vs baseline: 3.7821x; 1.0062x over previous
#include <cuda_runtime.h>
#include <cuda_bf16.h>
#include <cstdint>

// Problem constants
#define Bv   2
#define Sv   2048
#define Hv   16
#define Dv   64
#define Ev   1024
#define MTOK (Bv * Sv)   // 4096 tokens
#define EE   (Ev * Ev)

// ---------------------------------------------------------------------------
// Scratch (device globals — no allocation allowed)
// ---------------------------------------------------------------------------
__device__ __nv_bfloat16 g_qhi[MTOK * Ev], g_qlo[MTOK * Ev];
__device__ __nv_bfloat16 g_khi[MTOK * Ev], g_klo[MTOK * Ev];
__device__ __nv_bfloat16 g_vhi[MTOK * Ev], g_vlo[MTOK * Ev];
__device__ __nv_bfloat16 g_aohi[MTOK * Ev], g_aolo[MTOK * Ev];
__device__ __nv_bfloat16 g_xhi[MTOK * Ev], g_xlo[MTOK * Ev];
__device__ __nv_bfloat16 g_wthi[4][EE];   // W^T bf16 hi  [N,K]
__device__ __nv_bfloat16 g_wtlo[4][EE];   // W^T bf16 lo  [N,K]

// ---------------------------------------------------------------------------
// PTX helpers (baseline sm_80+)
// ---------------------------------------------------------------------------
__device__ __forceinline__ uint32_t smem_to_u32(const void* p) {
    uint32_t a;
    asm("{ .reg .u64 t; cvta.to.shared.u64 t, %1; cvt.u32.u64 %0, t; }"
        : "=r"(a) : "l"(p));
    return a;
}
__device__ __forceinline__ void cp_async16(uint32_t smem, const void* gmem) {
    asm volatile("cp.async.cg.shared.global [%0], [%1], 16;"
                 :: "r"(smem), "l"(gmem));
}
#define CP_COMMIT() asm volatile("cp.async.commit_group;" ::: "memory")
#define CP_WAIT1()  asm volatile("cp.async.wait_group 1;"  ::: "memory")

__device__ __forceinline__ void ldsm_x4(uint32_t* r, uint32_t addr) {
    asm volatile("ldmatrix.sync.aligned.m8n8.x4.shared.b16 {%0,%1,%2,%3}, [%4];"
                 : "=r"(r[0]), "=r"(r[1]), "=r"(r[2]), "=r"(r[3]) : "r"(addr));
}
__device__ __forceinline__ void ldsm_x4_t(uint32_t* r, uint32_t addr) {
    asm volatile("ldmatrix.sync.aligned.m8n8.x4.trans.shared.b16 {%0,%1,%2,%3}, [%4];"
                 : "=r"(r[0]), "=r"(r[1]), "=r"(r[2]), "=r"(r[3]) : "r"(addr));
}
__device__ __forceinline__ void mma16816(float* d, const uint32_t* a,
                                         uint32_t b0, uint32_t b1) {
    asm volatile(
        "mma.sync.aligned.m16n8k16.row.col.f32.bf16.bf16.f32 "
        "{%0,%1,%2,%3}, {%4,%5,%6,%7}, {%8,%9}, {%0,%1,%2,%3};"
        : "+f"(d[0]), "+f"(d[1]), "+f"(d[2]), "+f"(d[3])
        : "r"(a[0]), "r"(a[1]), "r"(a[2]), "r"(a[3]), "r"(b0), "r"(b1));
}
__device__ __forceinline__ uint32_t pack_hi_trunc(float a, float b) {
    uint32_t r;
    asm("prmt.b32 %0, %1, %2, 0x7632;" : "=r"(r)
        : "r"(__float_as_uint(a)), "r"(__float_as_uint(b)));
    return r;
}
__device__ __forceinline__ float trunc_hi(float a) {
    return __uint_as_float(__float_as_uint(a) & 0xFFFF0000u);
}
__device__ __forceinline__ uint32_t pack_bf16(float a, float b) {
    uint32_t r;
    asm("cvt.rn.bf16x2.f32 %0, %1, %2;" : "=r"(r) : "f"(b), "f"(a));
    return r;
}
__device__ __forceinline__ float ex2(float x) {
    float r; asm("ex2.approx.f32 %0, %1;" : "=f"(r) : "f"(x)); return r;
}

// ---------------------------------------------------------------------------
// fp32 -> bf16 hi/lo split, vectorized (4 elems/thread)
// ---------------------------------------------------------------------------
__global__ __launch_bounds__(256) void split_hi_lo4(const float* __restrict__ in,
                                                    __nv_bfloat16* __restrict__ hi,
                                                    __nv_bfloat16* __restrict__ lo,
                                                    int n) {
    int i = (blockIdx.x * 256 + threadIdx.x) * 4;
    if (i < n) {
        float4 v = *(const float4*)(in + i);
        uint32_t h0 = pack_bf16(v.x, v.y);
        uint32_t h1 = pack_bf16(v.z, v.w);
        float hx = __uint_as_float(h0 << 16), hy = __uint_as_float(h0 & 0xFFFF0000u);
        float hz = __uint_as_float(h1 << 16), hw = __uint_as_float(h1 & 0xFFFF0000u);
        uint32_t l0 = pack_bf16(v.x - hx, v.y - hy);
        uint32_t l1 = pack_bf16(v.z - hz, v.w - hw);
        *(uint2*)(hi + i) = make_uint2(h0, h1);
        *(uint2*)(lo + i) = make_uint2(l0, l1);
    }
}

// ---------------------------------------------------------------------------
// Transpose + split, all 4 weights in one launch (blockIdx.z selects W)
// ---------------------------------------------------------------------------
__global__ __launch_bounds__(256) void transpose_split4(
    const float* __restrict__ W0, const float* __restrict__ W1,
    const float* __restrict__ W2, const float* __restrict__ W3,
    __nv_bfloat16* __restrict__ ThiB, __nv_bfloat16* __restrict__ TloB) {
    __shared__ float t[32][33];
    const float* W = (blockIdx.z == 0) ? W0 : (blockIdx.z == 1) ? W1
                    : (blockIdx.z == 2) ? W2 : W3;
    __nv_bfloat16* Thi = ThiB + (size_t)blockIdx.z * EE;
    __nv_bfloat16* Tlo = TloB + (size_t)blockIdx.z * EE;
    int n0 = blockIdx.x * 32, k0 = blockIdx.y * 32;
    int tx = threadIdx.x, ty = threadIdx.y;
    for (int i = ty; i < 32; i += 8)
        t[i][tx] = W[(size_t)(k0 + i) * Ev + n0 + tx];
    __syncthreads();
    for (int i = ty; i < 32; i += 8) {
        float v = t[tx][i];
        __nv_bfloat16 h = __float2bfloat16(v);
        size_t idx = (size_t)(n0 + i) * Ev + k0 + tx;
        Thi[idx] = h;
        Tlo[idx] = __float2bfloat16(v - __bfloat162float(h));
    }
}

// ---------------------------------------------------------------------------
// HMMA GEMM: 128x128x32 CTA tile, bf16x3 split, 3-stage cp.async.
// MODE 0: out-projection, single W (index 3), fp32 C out.
// MODE 1: fused QKV, blockIdx.x in [0,24): w = bx>>3, write bf16 hi/lo.
// ---------------------------------------------------------------------------
#define BM 128
#define BN 128
#define BK 32
#define STAGES 3
#define TILE_B  8192u
#define STAGE_B (4u * TILE_B)
#define GEMM_SMEM (STAGES * STAGE_B)   // 96 KB
#define NCHUNK (Ev / BK)               // 32

template <int MODE>
__global__ __launch_bounds__(256, 1) void gemm_hmma_bf16x3(
    const __nv_bfloat16* __restrict__ Ahi, const __nv_bfloat16* __restrict__ Alo,
    const __nv_bfloat16* __restrict__ WThi, const __nv_bfloat16* __restrict__ WTlo,
    float* __restrict__ C,
    __nv_bfloat16* __restrict__ O0h, __nv_bfloat16* __restrict__ O0l,
    __nv_bfloat16* __restrict__ O1h, __nv_bfloat16* __restrict__ O1l,
    __nv_bfloat16* __restrict__ O2h, __nv_bfloat16* __restrict__ O2l) {
    extern __shared__ char smc[];
    const uint32_t sbase = smem_to_u32(smc);
    const int tid  = threadIdx.x;
    const int lane = tid & 31;
    const int wid  = tid >> 5;
    const int warp_m = wid & 1;
    const int warp_n = wid >> 1;
    const int m0 = blockIdx.y * BM;
    const int K = Ev, N = Ev;

    const __nv_bfloat16 *Bhi, *Blo;
    __nv_bfloat16 *Chi = nullptr, *Clo = nullptr;
    int n0;
    if (MODE == 0) {
        Bhi = WThi + (size_t)3 * EE;
        Blo = WTlo + (size_t)3 * EE;
        n0 = blockIdx.x * BN;
    } else {
        int w = blockIdx.x >> 3;
        n0 = (blockIdx.x & 7) * BN;
        Bhi = WThi + (size_t)w * EE;
        Blo = WTlo + (size_t)w * EE;
        Chi = (w == 0) ? O0h : (w == 1) ? O1h : O2h;
        Clo = (w == 0) ? O0l : (w == 1) ? O1l : O2l;
    }

    auto load_stage = [&](int kc, int s) {
        uint32_t st = sbase + (uint32_t)s * STAGE_B;
#pragma unroll
        for (int half = 0; half < 2; half++) {
            int q   = tid + half * 256;
            int row = q >> 2;
            int ch  = q & 3;
            uint32_t sw = (uint32_t)(row * 64 + ((ch ^ ((row >> 1) & 3)) * 16));
            size_t ga = (size_t)(m0 + row) * K + kc * BK + ch * 8;
            size_t gb = (size_t)(n0 + row) * K + kc * BK + ch * 8;
            cp_async16(st + 0 * TILE_B + sw, Ahi + ga);
            cp_async16(st + 1 * TILE_B + sw, Alo + ga);
            cp_async16(st + 2 * TILE_B + sw, Bhi + gb);
            cp_async16(st + 3 * TILE_B + sw, Blo + gb);
        }
    };

    float acc[4][4][4];
#pragma unroll
    for (int mt = 0; mt < 4; mt++)
#pragma unroll
        for (int nt = 0; nt < 4; nt++)
#pragma unroll
            for (int e = 0; e < 4; e++) acc[mt][nt][e] = 0.0f;

    load_stage(0, 0); CP_COMMIT();
    load_stage(1, 1); CP_COMMIT();

    const int sub = lane >> 3;
    const int r8  = lane & 7;

    for (int c = 0; c < NCHUNK; c++) {
        CP_WAIT1();
        __syncthreads();
        uint32_t st = sbase + (uint32_t)(c % STAGES) * STAGE_B;

#pragma unroll
        for (int ks = 0; ks < 2; ks++) {
            const int ch = ks * 2 + (sub >> 1);
            uint32_t ahi[4][4], alo[4][4];
#pragma unroll
            for (int mt = 0; mt < 4; mt++) {
                int row = warp_m * 64 + mt * 16 + (sub & 1) * 8 + r8;
                uint32_t addr = st + (uint32_t)(row * 64 + ((ch ^ ((row >> 1) & 3)) * 16));
                ldsm_x4(ahi[mt], addr);
                ldsm_x4(alo[mt], addr + TILE_B);
            }
            uint32_t bhi[2][4], blo[2][4];
#pragma unroll
            for (int np = 0; np < 2; np++) {
                int row = warp_n * 32 + np * 16 + (sub & 1) * 8 + r8;
                uint32_t addr = st + 2 * TILE_B +
                                (uint32_t)(row * 64 + ((ch ^ ((row >> 1) & 3)) * 16));
                ldsm_x4(bhi[np], addr);
                ldsm_x4(blo[np], addr + TILE_B);
            }
#pragma unroll
            for (int mt = 0; mt < 4; mt++)
#pragma unroll
                for (int nt = 0; nt < 4; nt++) {
                    uint32_t b0h = bhi[nt >> 1][nt & 1], b1h = bhi[nt >> 1][2 + (nt & 1)];
                    uint32_t b0l = blo[nt >> 1][nt & 1], b1l = blo[nt >> 1][2 + (nt & 1)];
                    mma16816(acc[mt][nt], ahi[mt], b0h, b1h);
                    mma16816(acc[mt][nt], ahi[mt], b0l, b1l);
                    mma16816(acc[mt][nt], alo[mt], b0h, b1h);
                }
        }
        __syncthreads();
        if (c + STAGES - 1 < NCHUNK) load_stage(c + STAGES - 1, (c + STAGES - 1) % STAGES);
        CP_COMMIT();
    }

    const int g   = lane >> 2;
    const int tig = lane & 3;
#pragma unroll
    for (int mt = 0; mt < 4; mt++) {
        int r0 = m0 + warp_m * 64 + mt * 16 + g;
#pragma unroll
        for (int nt = 0; nt < 4; nt++) {
            int col = n0 + warp_n * 32 + nt * 8 + tig * 2;
            float* a = acc[mt][nt];
            if (MODE == 1) {
                *(uint32_t*)&Chi[(size_t)r0 * N + col] = pack_hi_trunc(a[0], a[1]);
                *(uint32_t*)&Clo[(size_t)r0 * N + col] =
                    pack_bf16(a[0] - trunc_hi(a[0]), a[1] - trunc_hi(a[1]));
                *(uint32_t*)&Chi[(size_t)(r0 + 8) * N + col] = pack_hi_trunc(a[2], a[3]);
                *(uint32_t*)&Clo[(size_t)(r0 + 8) * N + col] =
                    pack_bf16(a[2] - trunc_hi(a[2]), a[3] - trunc_hi(a[3]));
            } else {
                *(float2*)&C[(size_t)r0 * N + col]       = make_float2(a[0], a[1]);
                *(float2*)&C[(size_t)(r0 + 8) * N + col] = make_float2(a[2], a[3]);
            }
        }
    }
}

// ---------------------------------------------------------------------------
// HMMA flash attention (causal). CTA: 128 q-rows x one head. 8 warps x 16 rows.
// KV tile = 128 rows, double-buffered cp.async.
// Smem: Qhi/Qlo 32K | 2 stages x (Khi Klo Vhi Vlo @16K) = 160K total.
// ---------------------------------------------------------------------------
#define ATT_STAGE 65536
#define ATT_SMEM (32768 + 2 * ATT_STAGE)

__global__ __launch_bounds__(256, 1) void attn_hmma(
    const __nv_bfloat16* __restrict__ Qhi, const __nv_bfloat16* __restrict__ Qlo,
    const __nv_bfloat16* __restrict__ Khi, const __nv_bfloat16* __restrict__ Klo,
    const __nv_bfloat16* __restrict__ Vhi, const __nv_bfloat16* __restrict__ Vlo,
    __nv_bfloat16* __restrict__ AOhi, __nv_bfloat16* __restrict__ AOlo) {
    extern __shared__ char smc[];
    const uint32_t sb = smem_to_u32(smc);
    const int tid = threadIdx.x, lane = tid & 31, wid = tid >> 5;
    const int qt = (int)gridDim.x - 1 - (int)blockIdx.x;  // heavy tiles first
    const int bh = blockIdx.y;
    const int b  = bh >> 4, h = bh & 15;
    const size_t base = (size_t)(b * Sv) * Ev + h * Dv;

    const int sub = lane >> 3, r8 = lane & 7, g = lane >> 2, tig = lane & 3;

    const uint32_t sQhi = sb, sQlo = sb + 16384;
    auto stage = [&](int s) { return sb + 32768 + (uint32_t)s * ATT_STAGE; };
    auto sw = [](int row, int ch) {
        return (uint32_t)(row * 128 + ((ch ^ (row & 7)) * 16));
    };

    // Q tile loads (group 0, together with KV tile 0)
    {
        const __nv_bfloat16* q0 = Qhi + base + (size_t)(qt * 128) * Ev;
        const __nv_bfloat16* q1 = Qlo + base + (size_t)(qt * 128) * Ev;
        for (int i = tid; i < 1024; i += 256) {
            int row = i >> 3, ch = i & 7;
            size_t off = (size_t)row * Ev + ch * 8;
            cp_async16(sQhi + sw(row, ch), q0 + off);
            cp_async16(sQlo + sw(row, ch), q1 + off);
        }
    }
    auto loadKV = [&](int j, int s) {
        uint32_t st = stage(s);
        const __nv_bfloat16* kh = Khi + base + (size_t)(j * 128) * Ev;
        const __nv_bfloat16* kl = Klo + base + (size_t)(j * 128) * Ev;
        const __nv_bfloat16* vh = Vhi + base + (size_t)(j * 128) * Ev;
        const __nv_bfloat16* vl = Vlo + base + (size_t)(j * 128) * Ev;
#pragma unroll
        for (int rep = 0; rep < 4; rep++) {
            int i = tid + rep * 256;           // 0..1023
            int row = i >> 3, ch = i & 7;
            size_t off = (size_t)row * Ev + ch * 8;
            uint32_t d = sw(row, ch);
            cp_async16(st + d,         kh + off);
            cp_async16(st + 16384 + d, kl + off);
            cp_async16(st + 32768 + d, vh + off);
            cp_async16(st + 49152 + d, vl + off);
        }
    };
    loadKV(0, 0); CP_COMMIT();

    const int ntiles = qt + 1;
    const int wr0 = qt * 128 + wid * 16;
    const float Cc = 0.125f * 1.44269504f;     // scale * log2(e)

    float m0 = -1e30f, m1 = -1e30f, l0 = 0.f, l1 = 0.f;
    float o[8][4];
#pragma unroll
    for (int nt = 0; nt < 8; nt++)
#pragma unroll
        for (int e = 0; e < 4; e++) o[nt][e] = 0.f;
    uint32_t qh[4][4], ql[4][4];

    for (int j = 0; j < ntiles; j++) {
        __syncthreads();
        if (j + 1 < ntiles) loadKV(j + 1, (j + 1) & 1);
        CP_COMMIT();
        CP_WAIT1();
        __syncthreads();
        uint32_t st = stage(j & 1);

        if (j == 0) {
#pragma unroll
            for (int ks = 0; ks < 4; ks++) {
                int row = wid * 16 + (sub & 1) * 8 + r8;
                int ch  = ks * 2 + (sub >> 1);
                ldsm_x4(qh[ks], sQhi + sw(row, ch));
                ldsm_x4(ql[ks], sQlo + sw(row, ch));
            }
        }

        // ---- S = Q K^T over 128 kv cols (3-term split) ----
        float s[16][4];
#pragma unroll
        for (int nt = 0; nt < 16; nt++)
#pragma unroll
            for (int e = 0; e < 4; e++) s[nt][e] = 0.f;

#pragma unroll
        for (int ks = 0; ks < 4; ks++) {
#pragma unroll
            for (int half = 0; half < 2; half++) {
                uint32_t kh4[4][4], kl4[4][4];
#pragma unroll
                for (int np = 0; np < 4; np++) {
                    int row = (half * 4 + np) * 16 + (sub & 1) * 8 + r8;
                    int ch  = ks * 2 + (sub >> 1);
                    uint32_t a = st + sw(row, ch);
                    ldsm_x4(kh4[np], a);
                    ldsm_x4(kl4[np], a + 16384);
                }
#pragma unroll
                for (int nt = 0; nt < 8; nt++) {
                    float* sg = s[half * 8 + nt];
                    uint32_t b0h = kh4[nt >> 1][nt & 1], b1h = kh4[nt >> 1][2 + (nt & 1)];
                    uint32_t b0l = kl4[nt >> 1][nt & 1], b1l = kl4[nt >> 1][2 + (nt & 1)];
                    mma16816(sg, qh[ks], b0h, b1h);
                    mma16816(sg, qh[ks], b0l, b1l);
                    mma16816(sg, ql[ks], b0h, b1h);
                }
            }
        }

        // ---- causal mask (diagonal tile only) ----
        if (j == qt) {
            int colb = j * 128;
            int row0 = wr0 + g, row1 = row0 + 8;
#pragma unroll
            for (int nt = 0; nt < 16; nt++) {
                int c0 = colb + nt * 8 + tig * 2;
                if (c0     > row0) s[nt][0] = -1e30f;
                if (c0 + 1 > row0) s[nt][1] = -1e30f;
                if (c0     > row1) s[nt][2] = -1e30f;
                if (c0 + 1 > row1) s[nt][3] = -1e30f;
            }
        }

        // ---- online softmax ----
        float mx0 = -1e30f, mx1 = -1e30f;
#pragma unroll
        for (int nt = 0; nt < 16; nt++) {
            mx0 = fmaxf(mx0, fmaxf(s[nt][0], s[nt][1]));
            mx1 = fmaxf(mx1, fmaxf(s[nt][2], s[nt][3]));
        }
        mx0 = fmaxf(mx0, __shfl_xor_sync(0xffffffffu, mx0, 1));
        mx0 = fmaxf(mx0, __shfl_xor_sync(0xffffffffu, mx0, 2));
        mx1 = fmaxf(mx1, __shfl_xor_sync(0xffffffffu, mx1, 1));
        mx1 = fmaxf(mx1, __shfl_xor_sync(0xffffffffu, mx1, 2));
        float nm0 = fmaxf(m0, mx0), nm1 = fmaxf(m1, mx1);
        float cr0 = ex2((m0 - nm0) * Cc), cr1 = ex2((m1 - nm1) * Cc);
        m0 = nm0; m1 = nm1;
        float rs0 = 0.f, rs1 = 0.f;
#pragma unroll
        for (int nt = 0; nt < 16; nt++) {
            s[nt][0] = ex2((s[nt][0] - m0) * Cc); rs0 += s[nt][0];
            s[nt][1] = ex2((s[nt][1] - m0) * Cc); rs0 += s[nt][1];
            s[nt][2] = ex2((s[nt][2] - m1) * Cc); rs1 += s[nt][2];
            s[nt][3] = ex2((s[nt][3] - m1) * Cc); rs1 += s[nt][3];
        }
        rs0 += __shfl_xor_sync(0xffffffffu, rs0, 1);
        rs0 += __shfl_xor_sync(0xffffffffu, rs0, 2);
        rs1 += __shfl_xor_sync(0xffffffffu, rs1, 1);
        rs1 += __shfl_xor_sync(0xffffffffu, rs1, 2);
        l0 = l0 * cr0 + rs0;
        l1 = l1 * cr1 + rs1;
#pragma unroll
        for (int nt = 0; nt < 8; nt++) {
            o[nt][0] *= cr0; o[nt][1] *= cr0;
            o[nt][2] *= cr1; o[nt][3] *= cr1;
        }

        // ---- P fragments (trunc split, from acc layout) ----
        uint32_t ph[8][4], pl[8][4];
#pragma unroll
        for (int j2 = 0; j2 < 8; j2++) {
            float* e0 = s[2 * j2];
            float* e1 = s[2 * j2 + 1];
            ph[j2][0] = pack_hi_trunc(e0[0], e0[1]);
            ph[j2][1] = pack_hi_trunc(e0[2], e0[3]);
            ph[j2][2] = pack_hi_trunc(e1[0], e1[1]);
            ph[j2][3] = pack_hi_trunc(e1[2], e1[3]);
            pl[j2][0] = pack_bf16(e0[0] - trunc_hi(e0[0]), e0[1] - trunc_hi(e0[1]));
            pl[j2][1] = pack_bf16(e0[2] - trunc_hi(e0[2]), e0[3] - trunc_hi(e0[3]));
            pl[j2][2] = pack_bf16(e1[0] - trunc_hi(e1[0]), e1[1] - trunc_hi(e1[1]));
            pl[j2][3] = pack_bf16(e1[2] - trunc_hi(e1[2]), e1[3] - trunc_hi(e1[3]));
        }

        // ---- O += P V (V via ldmatrix.trans; 3-term split) ----
#pragma unroll
        for (int ks = 0; ks < 8; ks++) {        // 128 kv rows = 8 k16 steps
#pragma unroll
            for (int dv = 0; dv < 4; dv++) {    // d in 16-col pairs
                int row = ks * 16 + (sub & 1) * 8 + r8;
                int ch  = dv * 2 + (sub >> 1);
                uint32_t a = st + sw(row, ch);
                uint32_t vh4[4], vl4[4];
                ldsm_x4_t(vh4, a + 32768);
                ldsm_x4_t(vl4, a + 49152);
                mma16816(o[2 * dv],     ph[ks], vh4[0], vh4[1]);
                mma16816(o[2 * dv],     ph[ks], vl4[0], vl4[1]);
                mma16816(o[2 * dv],     pl[ks], vh4[0], vh4[1]);
                mma16816(o[2 * dv + 1], ph[ks], vh4[2], vh4[3]);
                mma16816(o[2 * dv + 1], ph[ks], vl4[2], vl4[3]);
                mma16816(o[2 * dv + 1], pl[ks], vh4[2], vh4[3]);
            }
        }
    }

    // ---- normalize + write AO bf16 hi/lo ----
    float i0 = 1.0f / l0, i1 = 1.0f / l1;
    int t0 = qt * 128 + wid * 16 + g, t1 = t0 + 8;
#pragma unroll
    for (int nt = 0; nt < 8; nt++) {
        int col = nt * 8 + tig * 2;
        float a0 = o[nt][0] * i0, a1 = o[nt][1] * i0;
        float a2 = o[nt][2] * i1, a3 = o[nt][3] * i1;
        *(uint32_t*)&AOhi[base + (size_t)t0 * Ev + col] = pack_hi_trunc(a0, a1);
        *(uint32_t*)&AOlo[base + (size_t)t0 * Ev + col] =
            pack_bf16(a0 - trunc_hi(a0), a1 - trunc_hi(a1));
        *(uint32_t*)&AOhi[base + (size_t)t1 * Ev + col] = pack_hi_trunc(a2, a3);
        *(uint32_t*)&AOlo[base + (size_t)t1 * Ev + col] =
            pack_bf16(a2 - trunc_hi(a2), a3 - trunc_hi(a3));
    }
}

// ---------------------------------------------------------------------------
// Launch
// ---------------------------------------------------------------------------
extern "C" void kernel_launch(void* const* d_in, const int* in_sizes, int n_in,
                              void* d_out, int out_size) {
    const float* x  = (const float*)d_in[0];
    const float* Wq = (const float*)d_in[1];
    const float* Wk = (const float*)d_in[2];
    const float* Wv = (const float*)d_in[3];
    const float* Wo = (const float*)d_in[4];
    float* out = (float*)d_out;

    __nv_bfloat16 *qhi, *qlo, *khi, *klo, *vhi, *vlo, *aohi, *aolo;
    __nv_bfloat16 *xhi, *xlo, *wthi, *wtlo;
    cudaGetSymbolAddress((void**)&qhi,  g_qhi);
    cudaGetSymbolAddress((void**)&qlo,  g_qlo);
    cudaGetSymbolAddress((void**)&khi,  g_khi);
    cudaGetSymbolAddress((void**)&klo,  g_klo);
    cudaGetSymbolAddress((void**)&vhi,  g_vhi);
    cudaGetSymbolAddress((void**)&vlo,  g_vlo);
    cudaGetSymbolAddress((void**)&aohi, g_aohi);
    cudaGetSymbolAddress((void**)&aolo, g_aolo);
    cudaGetSymbolAddress((void**)&xhi,  g_xhi);
    cudaGetSymbolAddress((void**)&xlo,  g_xlo);
    cudaGetSymbolAddress((void**)&wthi, g_wthi);
    cudaGetSymbolAddress((void**)&wtlo, g_wtlo);

    static bool attr_set = false;
    if (!attr_set) {
        cudaFuncSetAttribute(gemm_hmma_bf16x3<0>,
                             cudaFuncAttributeMaxDynamicSharedMemorySize, GEMM_SMEM);
        cudaFuncSetAttribute(gemm_hmma_bf16x3<1>,
                             cudaFuncAttributeMaxDynamicSharedMemorySize, GEMM_SMEM);
        cudaFuncSetAttribute(attn_hmma,
                             cudaFuncAttributeMaxDynamicSharedMemorySize, ATT_SMEM);
        attr_set = true;
    }

    const int nElem = MTOK * Ev;

    // 1. split x into bf16 hi/lo
    split_hi_lo4<<<nElem / 1024, 256>>>(x, xhi, xlo, nElem);

    // 2. transpose + split all 4 weights (one launch)
    dim3 tGrid(Ev / 32, Ev / 32, 4), tBlk(32, 8);
    transpose_split4<<<tGrid, tBlk>>>(Wq, Wk, Wv, Wo, wthi, wtlo);

    // 3. fused QKV projection (N = 3072)
    dim3 qkvGrid(24, MTOK / BM);
    gemm_hmma_bf16x3<1><<<qkvGrid, 256, GEMM_SMEM>>>(
        xhi, xlo, wthi, wtlo, nullptr,
        qhi, qlo, khi, klo, vhi, vlo);

    // 4. HMMA flash attention -> AO bf16 hi/lo
    dim3 attnGrid(Sv / 128, Bv * Hv);   // (16, 32)
    attn_hmma<<<attnGrid, 256, ATT_SMEM>>>(qhi, qlo, khi, klo, vhi, vlo,
                                           aohi, aolo);

    // 5. output projection -> fp32 out
    dim3 oGrid(Ev / BN, MTOK / BM);
    gemm_hmma_bf16x3<0><<<oGrid, 256, GEMM_SMEM>>>(
        aohi, aolo, wthi, wtlo, out,
        nullptr, nullptr, nullptr, nullptr, nullptr, nullptr);
}

// round 7
// speedup vs baseline: 5.2839x; 1.3971x over previous
#include <cuda_runtime.h>
#include <cuda_fp16.h>
#include <cstdint>

// Problem constants
#define Bv   2
#define Sv   2048
#define Hv   16
#define Dv   64
#define Ev   1024
#define MTOK (Bv * Sv)   // 4096 tokens
#define EE   (Ev * Ev)

// ---------------------------------------------------------------------------
// Scratch (device globals — no allocation allowed)
// ---------------------------------------------------------------------------
__device__ __half g_qh [MTOK * Ev];
__device__ __half g_khi[MTOK * Ev], g_klo[MTOK * Ev];
__device__ __half g_vhi[MTOK * Ev], g_vlo[MTOK * Ev];
__device__ __half g_aoh[MTOK * Ev];
__device__ __half g_xh [MTOK * Ev];
__device__ __half g_wthi[4][EE];   // W^T fp16 hi  [N,K]
__device__ __half g_wtlo[4][EE];   // W^T fp16 lo  [N,K]

// ---------------------------------------------------------------------------
// PTX helpers
// ---------------------------------------------------------------------------
__device__ __forceinline__ uint32_t smem_to_u32(const void* p) {
    uint32_t a;
    asm("{ .reg .u64 t; cvta.to.shared.u64 t, %1; cvt.u32.u64 %0, t; }"
        : "=r"(a) : "l"(p));
    return a;
}
__device__ __forceinline__ void cp_async16(uint32_t smem, const void* gmem) {
    asm volatile("cp.async.cg.shared.global [%0], [%1], 16;"
                 :: "r"(smem), "l"(gmem));
}
#define CP_COMMIT() asm volatile("cp.async.commit_group;" ::: "memory")
#define CP_WAIT1()  asm volatile("cp.async.wait_group 1;"  ::: "memory")

__device__ __forceinline__ void ldsm_x4(uint32_t* r, uint32_t addr) {
    asm volatile("ldmatrix.sync.aligned.m8n8.x4.shared.b16 {%0,%1,%2,%3}, [%4];"
                 : "=r"(r[0]), "=r"(r[1]), "=r"(r[2]), "=r"(r[3]) : "r"(addr));
}
__device__ __forceinline__ void ldsm_x4_t(uint32_t* r, uint32_t addr) {
    asm volatile("ldmatrix.sync.aligned.m8n8.x4.trans.shared.b16 {%0,%1,%2,%3}, [%4];"
                 : "=r"(r[0]), "=r"(r[1]), "=r"(r[2]), "=r"(r[3]) : "r"(addr));
}
__device__ __forceinline__ void mma16816(float* d, const uint32_t* a,
                                         uint32_t b0, uint32_t b1) {
    asm volatile(
        "mma.sync.aligned.m16n8k16.row.col.f32.f16.f16.f32 "
        "{%0,%1,%2,%3}, {%4,%5,%6,%7}, {%8,%9}, {%0,%1,%2,%3};"
        : "+f"(d[0]), "+f"(d[1]), "+f"(d[2]), "+f"(d[3])
        : "r"(a[0]), "r"(a[1]), "r"(a[2]), "r"(a[3]), "r"(b0), "r"(b1));
}
// {lo: rn(a), hi: rn(b)} fp16x2 pack
__device__ __forceinline__ uint32_t pack_f16(float a, float b) {
    uint32_t r;
    asm("cvt.rn.f16x2.f32 %0, %1, %2;" : "=r"(r) : "f"(b), "f"(a));
    return r;
}
__device__ __forceinline__ float2 unpack_f16(uint32_t p) {
    __half2 h = *reinterpret_cast<__half2*>(&p);
    return __half22float2(h);
}
__device__ __forceinline__ float ex2(float x) {
    float r; asm("ex2.approx.f32 %0, %1;" : "=f"(r) : "f"(x)); return r;
}

// ---------------------------------------------------------------------------
// fp32 -> fp16 (hi only), vectorized
// ---------------------------------------------------------------------------
__global__ __launch_bounds__(256) void split_hi4(const float* __restrict__ in,
                                                 __half* __restrict__ hi, int n) {
    int i = (blockIdx.x * 256 + threadIdx.x) * 4;
    if (i < n) {
        float4 v = *(const float4*)(in + i);
        *(uint2*)(hi + i) = make_uint2(pack_f16(v.x, v.y), pack_f16(v.z, v.w));
    }
}

// ---------------------------------------------------------------------------
// Transpose + fp16 hi/lo split, all 4 weights in one launch
// ---------------------------------------------------------------------------
__global__ __launch_bounds__(256) void transpose_split4(
    const float* __restrict__ W0, const float* __restrict__ W1,
    const float* __restrict__ W2, const float* __restrict__ W3,
    __half* __restrict__ ThiB, __half* __restrict__ TloB) {
    __shared__ float t[32][33];
    const float* W = (blockIdx.z == 0) ? W0 : (blockIdx.z == 1) ? W1
                    : (blockIdx.z == 2) ? W2 : W3;
    __half* Thi = ThiB + (size_t)blockIdx.z * EE;
    __half* Tlo = TloB + (size_t)blockIdx.z * EE;
    int n0 = blockIdx.x * 32, k0 = blockIdx.y * 32;
    int tx = threadIdx.x, ty = threadIdx.y;
    for (int i = ty; i < 32; i += 8)
        t[i][tx] = W[(size_t)(k0 + i) * Ev + n0 + tx];
    __syncthreads();
    for (int i = ty; i < 32; i += 8) {
        float v = t[tx][i];
        __half h = __float2half_rn(v);
        size_t idx = (size_t)(n0 + i) * Ev + k0 + tx;
        Thi[idx] = h;
        Tlo[idx] = __float2half_rn(v - __half2float(h));
    }
}

// ---------------------------------------------------------------------------
// HMMA GEMM fp16x2 (B-side compensated): C = A @ B^T,
// D = Ahi*Bhi + Ahi*Blo. 128x128x32 tile, 3-stage cp.async, 8 warps.
// MODE 0: out-projection (W index 3), fp32 C out.
// MODE 1: fused QKV (w = bx>>3): w0 -> Q hi only; w1 -> K hi/lo; w2 -> V hi/lo.
// ---------------------------------------------------------------------------
#define BM 128
#define BN 128
#define BK 32
#define STAGES 3
#define TILE_B  8192u                 // 128*32*2B
#define STAGE_B (3u * TILE_B)         // Ahi, Bhi, Blo
#define GEMM_SMEM (STAGES * STAGE_B)  // 72 KB
#define NCHUNK (Ev / BK)              // 32

template <int MODE>
__global__ __launch_bounds__(256, 1) void gemm_hmma_f16x2(
    const __half* __restrict__ Ah,
    const __half* __restrict__ WThi, const __half* __restrict__ WTlo,
    float* __restrict__ C,
    __half* __restrict__ O0h,
    __half* __restrict__ O1h, __half* __restrict__ O1l,
    __half* __restrict__ O2h, __half* __restrict__ O2l) {
    extern __shared__ char smc[];
    const uint32_t sbase = smem_to_u32(smc);
    const int tid  = threadIdx.x;
    const int lane = tid & 31;
    const int wid  = tid >> 5;
    const int warp_m = wid & 1;
    const int warp_n = wid >> 1;
    const int m0 = blockIdx.y * BM;
    const int K = Ev, N = Ev;

    const __half *Bhi, *Blo;
    int n0, w = 0;
    if (MODE == 0) {
        Bhi = WThi + (size_t)3 * EE;
        Blo = WTlo + (size_t)3 * EE;
        n0 = blockIdx.x * BN;
    } else {
        w = blockIdx.x >> 3;
        n0 = (blockIdx.x & 7) * BN;
        Bhi = WThi + (size_t)w * EE;
        Blo = WTlo + (size_t)w * EE;
    }

    auto load_stage = [&](int kc, int s) {
        uint32_t st = sbase + (uint32_t)s * STAGE_B;
#pragma unroll
        for (int half = 0; half < 2; half++) {
            int q   = tid + half * 256;
            int row = q >> 2;
            int ch  = q & 3;
            uint32_t sw = (uint32_t)(row * 64 + ((ch ^ ((row >> 1) & 3)) * 16));
            size_t ga = (size_t)(m0 + row) * K + kc * BK + ch * 8;
            size_t gb = (size_t)(n0 + row) * K + kc * BK + ch * 8;
            cp_async16(st + sw,              Ah  + ga);
            cp_async16(st + 8192 + sw,       Bhi + gb);
            cp_async16(st + 16384 + sw,      Blo + gb);
        }
    };

    float acc[4][4][4];
#pragma unroll
    for (int mt = 0; mt < 4; mt++)
#pragma unroll
        for (int nt = 0; nt < 4; nt++)
#pragma unroll
            for (int e = 0; e < 4; e++) acc[mt][nt][e] = 0.0f;

    load_stage(0, 0); CP_COMMIT();
    load_stage(1, 1); CP_COMMIT();

    const int sub = lane >> 3;
    const int r8  = lane & 7;

    for (int c = 0; c < NCHUNK; c++) {
        CP_WAIT1();
        __syncthreads();
        uint32_t st = sbase + (uint32_t)(c % STAGES) * STAGE_B;

#pragma unroll
        for (int ks = 0; ks < 2; ks++) {
            const int ch = ks * 2 + (sub >> 1);
            uint32_t ah[4][4];
#pragma unroll
            for (int mt = 0; mt < 4; mt++) {
                int row = warp_m * 64 + mt * 16 + (sub & 1) * 8 + r8;
                ldsm_x4(ah[mt], st + (uint32_t)(row * 64 + ((ch ^ ((row >> 1) & 3)) * 16)));
            }
            uint32_t bhi[2][4], blo[2][4];
#pragma unroll
            for (int np = 0; np < 2; np++) {
                int row = warp_n * 32 + np * 16 + (sub & 1) * 8 + r8;
                uint32_t addr = st + 8192 +
                                (uint32_t)(row * 64 + ((ch ^ ((row >> 1) & 3)) * 16));
                ldsm_x4(bhi[np], addr);
                ldsm_x4(blo[np], addr + 8192);
            }
#pragma unroll
            for (int mt = 0; mt < 4; mt++)
#pragma unroll
                for (int nt = 0; nt < 4; nt++) {
                    uint32_t b0h = bhi[nt >> 1][nt & 1], b1h = bhi[nt >> 1][2 + (nt & 1)];
                    uint32_t b0l = blo[nt >> 1][nt & 1], b1l = blo[nt >> 1][2 + (nt & 1)];
                    mma16816(acc[mt][nt], ah[mt], b0h, b1h);
                    mma16816(acc[mt][nt], ah[mt], b0l, b1l);
                }
        }
        __syncthreads();
        if (c + STAGES - 1 < NCHUNK) load_stage(c + STAGES - 1, (c + STAGES - 1) % STAGES);
        CP_COMMIT();
    }

    const int g   = lane >> 2;
    const int tig = lane & 3;
    __half* Chi = nullptr; __half* Clo = nullptr;
    if (MODE == 1) {
        Chi = (w == 0) ? O0h : (w == 1) ? O1h : O2h;
        Clo = (w == 1) ? O1l : O2l;
    }
#pragma unroll
    for (int mt = 0; mt < 4; mt++) {
        int r0 = m0 + warp_m * 64 + mt * 16 + g;
#pragma unroll
        for (int nt = 0; nt < 4; nt++) {
            int col = n0 + warp_n * 32 + nt * 8 + tig * 2;
            float* a = acc[mt][nt];
            if (MODE == 1) {
                uint32_t h0 = pack_f16(a[0], a[1]);
                uint32_t h1 = pack_f16(a[2], a[3]);
                *(uint32_t*)&Chi[(size_t)r0 * N + col]       = h0;
                *(uint32_t*)&Chi[(size_t)(r0 + 8) * N + col] = h1;
                if (w != 0) {
                    float2 v0 = unpack_f16(h0), v1 = unpack_f16(h1);
                    *(uint32_t*)&Clo[(size_t)r0 * N + col] =
                        pack_f16(a[0] - v0.x, a[1] - v0.y);
                    *(uint32_t*)&Clo[(size_t)(r0 + 8) * N + col] =
                        pack_f16(a[2] - v1.x, a[3] - v1.y);
                }
            } else {
                *(float2*)&C[(size_t)r0 * N + col]       = make_float2(a[0], a[1]);
                *(float2*)&C[(size_t)(r0 + 8) * N + col] = make_float2(a[2], a[3]);
            }
        }
    }
}

// ---------------------------------------------------------------------------
// HMMA flash attention (causal), fp16x2 B-side compensated.
// CTA: 128 threads (4 warps x 16 q-rows = 64 q-rows), KV tile 64, 2-stage.
// Smem: Qhi 8K | 2 x (Khi Klo Vhi Vlo @8K) = 72 KB -> 2 CTAs/SM.
// S = Qh*Khi + Qh*Klo ; P fp16 (rn) ; O += Ph*Vhi + Ph*Vlo.
// ---------------------------------------------------------------------------
#define ATT_STAGE 32768
#define ATT_SMEM (8192 + 2 * ATT_STAGE)   // 72 KB

__global__ __launch_bounds__(128, 2) void attn_hmma(
    const __half* __restrict__ Qh,
    const __half* __restrict__ Khi, const __half* __restrict__ Klo,
    const __half* __restrict__ Vhi, const __half* __restrict__ Vlo,
    __half* __restrict__ AOh) {
    extern __shared__ char smc[];
    const uint32_t sb = smem_to_u32(smc);
    const int tid = threadIdx.x, lane = tid & 31, wid = tid >> 5;
    const int qt = (int)gridDim.x - 1 - (int)blockIdx.x;  // heavy tiles first
    const int bh = blockIdx.y;
    const int b  = bh >> 4, h = bh & 15;
    const size_t base = (size_t)(b * Sv) * Ev + h * Dv;

    const int sub = lane >> 3, r8 = lane & 7, g = lane >> 2, tig = lane & 3;

    const uint32_t sQ = sb;
    auto stage = [&](int s) { return sb + 8192 + (uint32_t)s * ATT_STAGE; };
    auto sw = [](int row, int ch) {
        return (uint32_t)(row * 128 + ((ch ^ (row & 7)) * 16));
    };

    // Q tile (64 rows) — part of cp.async group 0
    {
        const __half* q0 = Qh + base + (size_t)(qt * 64) * Ev;
        for (int i = tid; i < 512; i += 128) {
            int row = i >> 3, ch = i & 7;
            cp_async16(sQ + sw(row, ch), q0 + (size_t)row * Ev + ch * 8);
        }
    }
    auto loadKV = [&](int j, int s) {
        uint32_t st = stage(s);
        const __half* kh = Khi + base + (size_t)(j * 64) * Ev;
        const __half* kl = Klo + base + (size_t)(j * 64) * Ev;
        const __half* vh = Vhi + base + (size_t)(j * 64) * Ev;
        const __half* vl = Vlo + base + (size_t)(j * 64) * Ev;
#pragma unroll
        for (int rep = 0; rep < 4; rep++) {
            int i = tid + rep * 128;           // 0..511
            int row = i >> 3, ch = i & 7;
            size_t off = (size_t)row * Ev + ch * 8;
            uint32_t d = sw(row, ch);
            cp_async16(st + d,         kh + off);
            cp_async16(st + 8192 + d,  kl + off);
            cp_async16(st + 16384 + d, vh + off);
            cp_async16(st + 24576 + d, vl + off);
        }
    };
    loadKV(0, 0); CP_COMMIT();

    const int ntiles = qt + 1;
    const int wr0 = qt * 64 + wid * 16;
    const float Cc = 0.125f * 1.44269504f;     // scale * log2(e)

    float m0 = -1e30f, m1 = -1e30f, l0 = 0.f, l1 = 0.f;
    float o[8][4];
#pragma unroll
    for (int nt = 0; nt < 8; nt++)
#pragma unroll
        for (int e = 0; e < 4; e++) o[nt][e] = 0.f;
    uint32_t qh[4][4];

    for (int j = 0; j < ntiles; j++) {
        __syncthreads();
        if (j + 1 < ntiles) loadKV(j + 1, (j + 1) & 1);
        CP_COMMIT();
        CP_WAIT1();
        __syncthreads();
        uint32_t st = stage(j & 1);

        if (j == 0) {
#pragma unroll
            for (int ks = 0; ks < 4; ks++) {
                int row = wid * 16 + (sub & 1) * 8 + r8;
                int ch  = ks * 2 + (sub >> 1);
                ldsm_x4(qh[ks], sQ + sw(row, ch));
            }
        }

        // ---- S = Q K^T (2-term: K compensated) ----
        float s[8][4];
#pragma unroll
        for (int nt = 0; nt < 8; nt++)
#pragma unroll
            for (int e = 0; e < 4; e++) s[nt][e] = 0.f;

#pragma unroll
        for (int ks = 0; ks < 4; ks++) {
            uint32_t kh4[4][4], kl4[4][4];
#pragma unroll
            for (int np = 0; np < 4; np++) {
                int row = np * 16 + (sub & 1) * 8 + r8;
                int ch  = ks * 2 + (sub >> 1);
                uint32_t a = st + sw(row, ch);
                ldsm_x4(kh4[np], a);
                ldsm_x4(kl4[np], a + 8192);
            }
#pragma unroll
            for (int nt = 0; nt < 8; nt++) {
                uint32_t b0h = kh4[nt >> 1][nt & 1], b1h = kh4[nt >> 1][2 + (nt & 1)];
                uint32_t b0l = kl4[nt >> 1][nt & 1], b1l = kl4[nt >> 1][2 + (nt & 1)];
                mma16816(s[nt], qh[ks], b0h, b1h);
                mma16816(s[nt], qh[ks], b0l, b1l);
            }
        }

        // ---- causal mask (diagonal tile only) ----
        if (j == qt) {
            int colb = j * 64;
            int row0 = wr0 + g, row1 = row0 + 8;
#pragma unroll
            for (int nt = 0; nt < 8; nt++) {
                int c0 = colb + nt * 8 + tig * 2;
                if (c0     > row0) s[nt][0] = -1e30f;
                if (c0 + 1 > row0) s[nt][1] = -1e30f;
                if (c0     > row1) s[nt][2] = -1e30f;
                if (c0 + 1 > row1) s[nt][3] = -1e30f;
            }
        }

        // ---- online softmax (2 rows/thread, quad shuffles) ----
        float mx0 = -1e30f, mx1 = -1e30f;
#pragma unroll
        for (int nt = 0; nt < 8; nt++) {
            mx0 = fmaxf(mx0, fmaxf(s[nt][0], s[nt][1]));
            mx1 = fmaxf(mx1, fmaxf(s[nt][2], s[nt][3]));
        }
        mx0 = fmaxf(mx0, __shfl_xor_sync(0xffffffffu, mx0, 1));
        mx0 = fmaxf(mx0, __shfl_xor_sync(0xffffffffu, mx0, 2));
        mx1 = fmaxf(mx1, __shfl_xor_sync(0xffffffffu, mx1, 1));
        mx1 = fmaxf(mx1, __shfl_xor_sync(0xffffffffu, mx1, 2));
        float nm0 = fmaxf(m0, mx0), nm1 = fmaxf(m1, mx1);
        float cr0 = ex2((m0 - nm0) * Cc), cr1 = ex2((m1 - nm1) * Cc);
        m0 = nm0; m1 = nm1;
        float rs0 = 0.f, rs1 = 0.f;
#pragma unroll
        for (int nt = 0; nt < 8; nt++) {
            s[nt][0] = ex2((s[nt][0] - m0) * Cc); rs0 += s[nt][0];
            s[nt][1] = ex2((s[nt][1] - m0) * Cc); rs0 += s[nt][1];
            s[nt][2] = ex2((s[nt][2] - m1) * Cc); rs1 += s[nt][2];
            s[nt][3] = ex2((s[nt][3] - m1) * Cc); rs1 += s[nt][3];
        }
        rs0 += __shfl_xor_sync(0xffffffffu, rs0, 1);
        rs0 += __shfl_xor_sync(0xffffffffu, rs0, 2);
        rs1 += __shfl_xor_sync(0xffffffffu, rs1, 1);
        rs1 += __shfl_xor_sync(0xffffffffu, rs1, 2);
        l0 = l0 * cr0 + rs0;
        l1 = l1 * cr1 + rs1;
#pragma unroll
        for (int nt = 0; nt < 8; nt++) {
            o[nt][0] *= cr0; o[nt][1] *= cr0;
            o[nt][2] *= cr1; o[nt][3] *= cr1;
        }

        // ---- P fragments (fp16 rn, straight from acc layout) ----
        uint32_t ph[4][4];
#pragma unroll
        for (int j2 = 0; j2 < 4; j2++) {
            float* e0 = s[2 * j2];
            float* e1 = s[2 * j2 + 1];
            ph[j2][0] = pack_f16(e0[0], e0[1]);
            ph[j2][1] = pack_f16(e0[2], e0[3]);
            ph[j2][2] = pack_f16(e1[0], e1[1]);
            ph[j2][3] = pack_f16(e1[2], e1[3]);
        }

        // ---- O += P V (V compensated; ldmatrix.trans) ----
#pragma unroll
        for (int ks = 0; ks < 4; ks++) {
#pragma unroll
            for (int dv = 0; dv < 4; dv++) {
                int row = ks * 16 + (sub & 1) * 8 + r8;
                int ch  = dv * 2 + (sub >> 1);
                uint32_t a = st + sw(row, ch);
                uint32_t vh4[4], vl4[4];
                ldsm_x4_t(vh4, a + 16384);
                ldsm_x4_t(vl4, a + 24576);
                mma16816(o[2 * dv],     ph[ks], vh4[0], vh4[1]);
                mma16816(o[2 * dv],     ph[ks], vl4[0], vl4[1]);
                mma16816(o[2 * dv + 1], ph[ks], vh4[2], vh4[3]);
                mma16816(o[2 * dv + 1], ph[ks], vl4[2], vl4[3]);
            }
        }
    }

    // ---- normalize + write AO fp16 hi ----
    float i0 = 1.0f / l0, i1 = 1.0f / l1;
    int t0 = qt * 64 + wid * 16 + g, t1 = t0 + 8;
#pragma unroll
    for (int nt = 0; nt < 8; nt++) {
        int col = nt * 8 + tig * 2;
        *(uint32_t*)&AOh[base + (size_t)t0 * Ev + col] =
            pack_f16(o[nt][0] * i0, o[nt][1] * i0);
        *(uint32_t*)&AOh[base + (size_t)t1 * Ev + col] =
            pack_f16(o[nt][2] * i1, o[nt][3] * i1);
    }
}

// ---------------------------------------------------------------------------
// Launch
// ---------------------------------------------------------------------------
extern "C" void kernel_launch(void* const* d_in, const int* in_sizes, int n_in,
                              void* d_out, int out_size) {
    const float* x  = (const float*)d_in[0];
    const float* Wq = (const float*)d_in[1];
    const float* Wk = (const float*)d_in[2];
    const float* Wv = (const float*)d_in[3];
    const float* Wo = (const float*)d_in[4];
    float* out = (float*)d_out;

    __half *qh, *khi, *klo, *vhi, *vlo, *aoh, *xh, *wthi, *wtlo;
    cudaGetSymbolAddress((void**)&qh,   g_qh);
    cudaGetSymbolAddress((void**)&khi,  g_khi);
    cudaGetSymbolAddress((void**)&klo,  g_klo);
    cudaGetSymbolAddress((void**)&vhi,  g_vhi);
    cudaGetSymbolAddress((void**)&vlo,  g_vlo);
    cudaGetSymbolAddress((void**)&aoh,  g_aoh);
    cudaGetSymbolAddress((void**)&xh,   g_xh);
    cudaGetSymbolAddress((void**)&wthi, g_wthi);
    cudaGetSymbolAddress((void**)&wtlo, g_wtlo);

    static bool attr_set = false;
    if (!attr_set) {
        cudaFuncSetAttribute(gemm_hmma_f16x2<0>,
                             cudaFuncAttributeMaxDynamicSharedMemorySize, GEMM_SMEM);
        cudaFuncSetAttribute(gemm_hmma_f16x2<1>,
                             cudaFuncAttributeMaxDynamicSharedMemorySize, GEMM_SMEM);
        cudaFuncSetAttribute(attn_hmma,
                             cudaFuncAttributeMaxDynamicSharedMemorySize, ATT_SMEM);
        attr_set = true;
    }

    const int nElem = MTOK * Ev;

    // 1. x -> fp16 hi
    split_hi4<<<nElem / 1024, 256>>>(x, xh, nElem);

    // 2. transpose + split all 4 weights
    dim3 tGrid(Ev / 32, Ev / 32, 4), tBlk(32, 8);
    transpose_split4<<<tGrid, tBlk>>>(Wq, Wk, Wv, Wo, wthi, wtlo);

    // 3. fused QKV projection (N = 3072)
    dim3 qkvGrid(24, MTOK / BM);
    gemm_hmma_f16x2<1><<<qkvGrid, 256, GEMM_SMEM>>>(
        xh, wthi, wtlo, nullptr, qh, khi, klo, vhi, vlo);

    // 4. flash attention (2 CTAs/SM)
    dim3 attnGrid(Sv / 64, Bv * Hv);   // (32, 32)
    attn_hmma<<<attnGrid, 128, ATT_SMEM>>>(qh, khi, klo, vhi, vlo, aoh);

    // 5. output projection -> fp32 out
    dim3 oGrid(Ev / BN, MTOK / BM);
    gemm_hmma_f16x2<0><<<oGrid, 256, GEMM_SMEM>>>(
        aoh, wthi, wtlo, out, nullptr, nullptr, nullptr, nullptr, nullptr);
}

// round 8
// speedup vs baseline: 5.8941x; 1.1155x over previous
#include <cuda_runtime.h>
#include <cuda_fp16.h>
#include <cstdint>

// Problem constants
#define Bv   2
#define Sv   2048
#define Hv   16
#define Dv   64
#define Ev   1024
#define MTOK (Bv * Sv)   // 4096 tokens
#define EE   (Ev * Ev)

// ---------------------------------------------------------------------------
// Scratch (device globals — no allocation allowed)
// ---------------------------------------------------------------------------
__device__ __half g_qh [MTOK * Ev];
__device__ __half g_khi[MTOK * Ev], g_klo[MTOK * Ev];
__device__ __half g_vhi[MTOK * Ev], g_vlo[MTOK * Ev];
__device__ __half g_aoh[MTOK * Ev];
__device__ __half g_xh [MTOK * Ev];
__device__ __half g_wthi[4][EE];   // W^T fp16 hi  [N,K]
__device__ __half g_wtlo[4][EE];   // W^T fp16 lo  [N,K]

// ---------------------------------------------------------------------------
// PTX helpers
// ---------------------------------------------------------------------------
__device__ __forceinline__ uint32_t smem_to_u32(const void* p) {
    uint32_t a;
    asm("{ .reg .u64 t; cvta.to.shared.u64 t, %1; cvt.u32.u64 %0, t; }"
        : "=r"(a) : "l"(p));
    return a;
}
__device__ __forceinline__ void cp_async16(uint32_t smem, const void* gmem) {
    asm volatile("cp.async.cg.shared.global [%0], [%1], 16;"
                 :: "r"(smem), "l"(gmem));
}
#define CP_COMMIT() asm volatile("cp.async.commit_group;" ::: "memory")
#define CP_WAIT1()  asm volatile("cp.async.wait_group 1;"  ::: "memory")

__device__ __forceinline__ void ldsm_x4(uint32_t* r, uint32_t addr) {
    asm volatile("ldmatrix.sync.aligned.m8n8.x4.shared.b16 {%0,%1,%2,%3}, [%4];"
                 : "=r"(r[0]), "=r"(r[1]), "=r"(r[2]), "=r"(r[3]) : "r"(addr));
}
__device__ __forceinline__ void ldsm_x4_t(uint32_t* r, uint32_t addr) {
    asm volatile("ldmatrix.sync.aligned.m8n8.x4.trans.shared.b16 {%0,%1,%2,%3}, [%4];"
                 : "=r"(r[0]), "=r"(r[1]), "=r"(r[2]), "=r"(r[3]) : "r"(addr));
}
__device__ __forceinline__ void mma16816(float* d, const uint32_t* a,
                                         uint32_t b0, uint32_t b1) {
    asm volatile(
        "mma.sync.aligned.m16n8k16.row.col.f32.f16.f16.f32 "
        "{%0,%1,%2,%3}, {%4,%5,%6,%7}, {%8,%9}, {%0,%1,%2,%3};"
        : "+f"(d[0]), "+f"(d[1]), "+f"(d[2]), "+f"(d[3])
        : "r"(a[0]), "r"(a[1]), "r"(a[2]), "r"(a[3]), "r"(b0), "r"(b1));
}
// {lo: rn(a), hi: rn(b)} fp16x2 pack
__device__ __forceinline__ uint32_t pack_f16(float a, float b) {
    uint32_t r;
    asm("cvt.rn.f16x2.f32 %0, %1, %2;" : "=r"(r) : "f"(b), "f"(a));
    return r;
}
__device__ __forceinline__ float2 unpack_f16(uint32_t p) {
    __half2 h = *reinterpret_cast<__half2*>(&p);
    return __half22float2(h);
}
__device__ __forceinline__ float ex2(float x) {
    float r; asm("ex2.approx.f32 %0, %1;" : "=f"(r) : "f"(x)); return r;
}

// ---------------------------------------------------------------------------
// fp32 -> fp16 (hi only), vectorized
// ---------------------------------------------------------------------------
__global__ __launch_bounds__(256) void split_hi4(const float* __restrict__ in,
                                                 __half* __restrict__ hi, int n) {
    int i = (blockIdx.x * 256 + threadIdx.x) * 4;
    if (i < n) {
        float4 v = *(const float4*)(in + i);
        *(uint2*)(hi + i) = make_uint2(pack_f16(v.x, v.y), pack_f16(v.z, v.w));
    }
}

// ---------------------------------------------------------------------------
// Transpose + fp16 hi/lo split, all 4 weights in one launch
// ---------------------------------------------------------------------------
__global__ __launch_bounds__(256) void transpose_split4(
    const float* __restrict__ W0, const float* __restrict__ W1,
    const float* __restrict__ W2, const float* __restrict__ W3,
    __half* __restrict__ ThiB, __half* __restrict__ TloB) {
    __shared__ float t[32][33];
    const float* W = (blockIdx.z == 0) ? W0 : (blockIdx.z == 1) ? W1
                    : (blockIdx.z == 2) ? W2 : W3;
    __half* Thi = ThiB + (size_t)blockIdx.z * EE;
    __half* Tlo = TloB + (size_t)blockIdx.z * EE;
    int n0 = blockIdx.x * 32, k0 = blockIdx.y * 32;
    int tx = threadIdx.x, ty = threadIdx.y;
    for (int i = ty; i < 32; i += 8)
        t[i][tx] = W[(size_t)(k0 + i) * Ev + n0 + tx];
    __syncthreads();
    for (int i = ty; i < 32; i += 8) {
        float v = t[tx][i];
        __half h = __float2half_rn(v);
        size_t idx = (size_t)(n0 + i) * Ev + k0 + tx;
        Thi[idx] = h;
        Tlo[idx] = __float2half_rn(v - __half2float(h));
    }
}

// ---------------------------------------------------------------------------
// HMMA GEMM fp16x2 (B-side compensated): C = A @ B^T,
// D = Ahi*Bhi + Ahi*Blo. 128x128x32 tile, 3-stage cp.async, 8 warps,
// 2 CTAs/SM (regs capped at 128 — watch for spills in post-mortem).
// MODE 0: out-projection (W index 3), fp32 C out.
// MODE 1: fused QKV (w = bx>>3): w0 -> Q hi only; w1 -> K hi/lo; w2 -> V hi/lo.
// ---------------------------------------------------------------------------
#define BM 128
#define BN 128
#define BK 32
#define STAGES 3
#define TILE_B  8192u                 // 128*32*2B
#define STAGE_B (3u * TILE_B)         // Ahi, Bhi, Blo
#define GEMM_SMEM (STAGES * STAGE_B)  // 72 KB
#define NCHUNK (Ev / BK)              // 32

template <int MODE>
__global__ __launch_bounds__(256, 2) void gemm_hmma_f16x2(
    const __half* __restrict__ Ah,
    const __half* __restrict__ WThi, const __half* __restrict__ WTlo,
    float* __restrict__ C,
    __half* __restrict__ O0h,
    __half* __restrict__ O1h, __half* __restrict__ O1l,
    __half* __restrict__ O2h, __half* __restrict__ O2l) {
    extern __shared__ char smc[];
    const uint32_t sbase = smem_to_u32(smc);
    const int tid  = threadIdx.x;
    const int lane = tid & 31;
    const int wid  = tid >> 5;
    const int warp_m = wid & 1;
    const int warp_n = wid >> 1;
    const int m0 = blockIdx.y * BM;
    const int K = Ev, N = Ev;

    const __half *Bhi, *Blo;
    int n0, w = 0;
    if (MODE == 0) {
        Bhi = WThi + (size_t)3 * EE;
        Blo = WTlo + (size_t)3 * EE;
        n0 = blockIdx.x * BN;
    } else {
        w = blockIdx.x >> 3;
        n0 = (blockIdx.x & 7) * BN;
        Bhi = WThi + (size_t)w * EE;
        Blo = WTlo + (size_t)w * EE;
    }

    auto load_stage = [&](int kc, int s) {
        uint32_t st = sbase + (uint32_t)s * STAGE_B;
#pragma unroll
        for (int half = 0; half < 2; half++) {
            int q   = tid + half * 256;
            int row = q >> 2;
            int ch  = q & 3;
            uint32_t sw = (uint32_t)(row * 64 + ((ch ^ ((row >> 1) & 3)) * 16));
            size_t ga = (size_t)(m0 + row) * K + kc * BK + ch * 8;
            size_t gb = (size_t)(n0 + row) * K + kc * BK + ch * 8;
            cp_async16(st + sw,              Ah  + ga);
            cp_async16(st + 8192 + sw,       Bhi + gb);
            cp_async16(st + 16384 + sw,      Blo + gb);
        }
    };

    float acc[4][4][4];
#pragma unroll
    for (int mt = 0; mt < 4; mt++)
#pragma unroll
        for (int nt = 0; nt < 4; nt++)
#pragma unroll
            for (int e = 0; e < 4; e++) acc[mt][nt][e] = 0.0f;

    load_stage(0, 0); CP_COMMIT();
    load_stage(1, 1); CP_COMMIT();

    const int sub = lane >> 3;
    const int r8  = lane & 7;

    for (int c = 0; c < NCHUNK; c++) {
        CP_WAIT1();
        __syncthreads();
        uint32_t st = sbase + (uint32_t)(c % STAGES) * STAGE_B;

#pragma unroll
        for (int ks = 0; ks < 2; ks++) {
            const int ch = ks * 2 + (sub >> 1);
            uint32_t ah[4][4];
#pragma unroll
            for (int mt = 0; mt < 4; mt++) {
                int row = warp_m * 64 + mt * 16 + (sub & 1) * 8 + r8;
                ldsm_x4(ah[mt], st + (uint32_t)(row * 64 + ((ch ^ ((row >> 1) & 3)) * 16)));
            }
            uint32_t bhi[2][4], blo[2][4];
#pragma unroll
            for (int np = 0; np < 2; np++) {
                int row = warp_n * 32 + np * 16 + (sub & 1) * 8 + r8;
                uint32_t addr = st + 8192 +
                                (uint32_t)(row * 64 + ((ch ^ ((row >> 1) & 3)) * 16));
                ldsm_x4(bhi[np], addr);
                ldsm_x4(blo[np], addr + 8192);
            }
#pragma unroll
            for (int mt = 0; mt < 4; mt++)
#pragma unroll
                for (int nt = 0; nt < 4; nt++) {
                    uint32_t b0h = bhi[nt >> 1][nt & 1], b1h = bhi[nt >> 1][2 + (nt & 1)];
                    uint32_t b0l = blo[nt >> 1][nt & 1], b1l = blo[nt >> 1][2 + (nt & 1)];
                    mma16816(acc[mt][nt], ah[mt], b0h, b1h);
                    mma16816(acc[mt][nt], ah[mt], b0l, b1l);
                }
        }
        __syncthreads();
        if (c + STAGES - 1 < NCHUNK) load_stage(c + STAGES - 1, (c + STAGES - 1) % STAGES);
        CP_COMMIT();
    }

    const int g   = lane >> 2;
    const int tig = lane & 3;
    __half* Chi = nullptr; __half* Clo = nullptr;
    if (MODE == 1) {
        Chi = (w == 0) ? O0h : (w == 1) ? O1h : O2h;
        Clo = (w == 1) ? O1l : O2l;
    }
#pragma unroll
    for (int mt = 0; mt < 4; mt++) {
        int r0 = m0 + warp_m * 64 + mt * 16 + g;
#pragma unroll
        for (int nt = 0; nt < 4; nt++) {
            int col = n0 + warp_n * 32 + nt * 8 + tig * 2;
            float* a = acc[mt][nt];
            if (MODE == 1) {
                uint32_t h0 = pack_f16(a[0], a[1]);
                uint32_t h1 = pack_f16(a[2], a[3]);
                *(uint32_t*)&Chi[(size_t)r0 * N + col]       = h0;
                *(uint32_t*)&Chi[(size_t)(r0 + 8) * N + col] = h1;
                if (w != 0) {
                    float2 v0 = unpack_f16(h0), v1 = unpack_f16(h1);
                    *(uint32_t*)&Clo[(size_t)r0 * N + col] =
                        pack_f16(a[0] - v0.x, a[1] - v0.y);
                    *(uint32_t*)&Clo[(size_t)(r0 + 8) * N + col] =
                        pack_f16(a[2] - v1.x, a[3] - v1.y);
                }
            } else {
                *(float2*)&C[(size_t)r0 * N + col]       = make_float2(a[0], a[1]);
                *(float2*)&C[(size_t)(r0 + 8) * N + col] = make_float2(a[2], a[3]);
            }
        }
    }
}

// ---------------------------------------------------------------------------
// HMMA flash attention (causal), fp16x2 B-side compensated.
// CTA: 128 threads (4 warps x 16 q-rows = 64 q-rows), KV tile 64, 2-stage.
// Smem: Qhi 8K | 2 x (Khi Klo Vhi Vlo @8K) = 72 KB -> 3 CTAs/SM (216 KB,
// regs capped at 170; kernel uses 168).
// S = Qh*Khi + Qh*Klo ; P fp16 (rn) ; O += Ph*Vhi + Ph*Vlo.
// ---------------------------------------------------------------------------
#define ATT_STAGE 32768
#define ATT_SMEM (8192 + 2 * ATT_STAGE)   // 72 KB

__global__ __launch_bounds__(128, 3) void attn_hmma(
    const __half* __restrict__ Qh,
    const __half* __restrict__ Khi, const __half* __restrict__ Klo,
    const __half* __restrict__ Vhi, const __half* __restrict__ Vlo,
    __half* __restrict__ AOh) {
    extern __shared__ char smc[];
    const uint32_t sb = smem_to_u32(smc);
    const int tid = threadIdx.x, lane = tid & 31, wid = tid >> 5;
    const int qt = (int)gridDim.x - 1 - (int)blockIdx.x;  // heavy tiles first
    const int bh = blockIdx.y;
    const int b  = bh >> 4, h = bh & 15;
    const size_t base = (size_t)(b * Sv) * Ev + h * Dv;

    const int sub = lane >> 3, r8 = lane & 7, g = lane >> 2, tig = lane & 3;

    const uint32_t sQ = sb;
    auto stage = [&](int s) { return sb + 8192 + (uint32_t)s * ATT_STAGE; };
    auto sw = [](int row, int ch) {
        return (uint32_t)(row * 128 + ((ch ^ (row & 7)) * 16));
    };

    // Q tile (64 rows) — part of cp.async group 0
    {
        const __half* q0 = Qh + base + (size_t)(qt * 64) * Ev;
        for (int i = tid; i < 512; i += 128) {
            int row = i >> 3, ch = i & 7;
            cp_async16(sQ + sw(row, ch), q0 + (size_t)row * Ev + ch * 8);
        }
    }
    auto loadKV = [&](int j, int s) {
        uint32_t st = stage(s);
        const __half* kh = Khi + base + (size_t)(j * 64) * Ev;
        const __half* kl = Klo + base + (size_t)(j * 64) * Ev;
        const __half* vh = Vhi + base + (size_t)(j * 64) * Ev;
        const __half* vl = Vlo + base + (size_t)(j * 64) * Ev;
#pragma unroll
        for (int rep = 0; rep < 4; rep++) {
            int i = tid + rep * 128;           // 0..511
            int row = i >> 3, ch = i & 7;
            size_t off = (size_t)row * Ev + ch * 8;
            uint32_t d = sw(row, ch);
            cp_async16(st + d,         kh + off);
            cp_async16(st + 8192 + d,  kl + off);
            cp_async16(st + 16384 + d, vh + off);
            cp_async16(st + 24576 + d, vl + off);
        }
    };
    loadKV(0, 0); CP_COMMIT();

    const int ntiles = qt + 1;
    const int wr0 = qt * 64 + wid * 16;
    const float Cc = 0.125f * 1.44269504f;     // scale * log2(e)

    float m0 = -1e30f, m1 = -1e30f, l0 = 0.f, l1 = 0.f;
    float o[8][4];
#pragma unroll
    for (int nt = 0; nt < 8; nt++)
#pragma unroll
        for (int e = 0; e < 4; e++) o[nt][e] = 0.f;
    uint32_t qh[4][4];

    for (int j = 0; j < ntiles; j++) {
        __syncthreads();
        if (j + 1 < ntiles) loadKV(j + 1, (j + 1) & 1);
        CP_COMMIT();
        CP_WAIT1();
        __syncthreads();
        uint32_t st = stage(j & 1);

        if (j == 0) {
#pragma unroll
            for (int ks = 0; ks < 4; ks++) {
                int row = wid * 16 + (sub & 1) * 8 + r8;
                int ch  = ks * 2 + (sub >> 1);
                ldsm_x4(qh[ks], sQ + sw(row, ch));
            }
        }

        // ---- S = Q K^T (2-term: K compensated) ----
        float s[8][4];
#pragma unroll
        for (int nt = 0; nt < 8; nt++)
#pragma unroll
            for (int e = 0; e < 4; e++) s[nt][e] = 0.f;

#pragma unroll
        for (int ks = 0; ks < 4; ks++) {
            uint32_t kh4[4][4], kl4[4][4];
#pragma unroll
            for (int np = 0; np < 4; np++) {
                int row = np * 16 + (sub & 1) * 8 + r8;
                int ch  = ks * 2 + (sub >> 1);
                uint32_t a = st + sw(row, ch);
                ldsm_x4(kh4[np], a);
                ldsm_x4(kl4[np], a + 8192);
            }
#pragma unroll
            for (int nt = 0; nt < 8; nt++) {
                uint32_t b0h = kh4[nt >> 1][nt & 1], b1h = kh4[nt >> 1][2 + (nt & 1)];
                uint32_t b0l = kl4[nt >> 1][nt & 1], b1l = kl4[nt >> 1][2 + (nt & 1)];
                mma16816(s[nt], qh[ks], b0h, b1h);
                mma16816(s[nt], qh[ks], b0l, b1l);
            }
        }

        // ---- causal mask (diagonal tile only) ----
        if (j == qt) {
            int colb = j * 64;
            int row0 = wr0 + g, row1 = row0 + 8;
#pragma unroll
            for (int nt = 0; nt < 8; nt++) {
                int c0 = colb + nt * 8 + tig * 2;
                if (c0     > row0) s[nt][0] = -1e30f;
                if (c0 + 1 > row0) s[nt][1] = -1e30f;
                if (c0     > row1) s[nt][2] = -1e30f;
                if (c0 + 1 > row1) s[nt][3] = -1e30f;
            }
        }

        // ---- online softmax (2 rows/thread, quad shuffles) ----
        float mx0 = -1e30f, mx1 = -1e30f;
#pragma unroll
        for (int nt = 0; nt < 8; nt++) {
            mx0 = fmaxf(mx0, fmaxf(s[nt][0], s[nt][1]));
            mx1 = fmaxf(mx1, fmaxf(s[nt][2], s[nt][3]));
        }
        mx0 = fmaxf(mx0, __shfl_xor_sync(0xffffffffu, mx0, 1));
        mx0 = fmaxf(mx0, __shfl_xor_sync(0xffffffffu, mx0, 2));
        mx1 = fmaxf(mx1, __shfl_xor_sync(0xffffffffu, mx1, 1));
        mx1 = fmaxf(mx1, __shfl_xor_sync(0xffffffffu, mx1, 2));
        float nm0 = fmaxf(m0, mx0), nm1 = fmaxf(m1, mx1);
        float cr0 = ex2((m0 - nm0) * Cc), cr1 = ex2((m1 - nm1) * Cc);
        m0 = nm0; m1 = nm1;
        float rs0 = 0.f, rs1 = 0.f;
#pragma unroll
        for (int nt = 0; nt < 8; nt++) {
            s[nt][0] = ex2((s[nt][0] - m0) * Cc); rs0 += s[nt][0];
            s[nt][1] = ex2((s[nt][1] - m0) * Cc); rs0 += s[nt][1];
            s[nt][2] = ex2((s[nt][2] - m1) * Cc); rs1 += s[nt][2];
            s[nt][3] = ex2((s[nt][3] - m1) * Cc); rs1 += s[nt][3];
        }
        rs0 += __shfl_xor_sync(0xffffffffu, rs0, 1);
        rs0 += __shfl_xor_sync(0xffffffffu, rs0, 2);
        rs1 += __shfl_xor_sync(0xffffffffu, rs1, 1);
        rs1 += __shfl_xor_sync(0xffffffffu, rs1, 2);
        l0 = l0 * cr0 + rs0;
        l1 = l1 * cr1 + rs1;
#pragma unroll
        for (int nt = 0; nt < 8; nt++) {
            o[nt][0] *= cr0; o[nt][1] *= cr0;
            o[nt][2] *= cr1; o[nt][3] *= cr1;
        }

        // ---- P fragments (fp16 rn, straight from acc layout) ----
        uint32_t ph[4][4];
#pragma unroll
        for (int j2 = 0; j2 < 4; j2++) {
            float* e0 = s[2 * j2];
            float* e1 = s[2 * j2 + 1];
            ph[j2][0] = pack_f16(e0[0], e0[1]);
            ph[j2][1] = pack_f16(e0[2], e0[3]);
            ph[j2][2] = pack_f16(e1[0], e1[1]);
            ph[j2][3] = pack_f16(e1[2], e1[3]);
        }

        // ---- O += P V (V compensated; ldmatrix.trans) ----
#pragma unroll
        for (int ks = 0; ks < 4; ks++) {
#pragma unroll
            for (int dv = 0; dv < 4; dv++) {
                int row = ks * 16 + (sub & 1) * 8 + r8;
                int ch  = dv * 2 + (sub >> 1);
                uint32_t a = st + sw(row, ch);
                uint32_t vh4[4], vl4[4];
                ldsm_x4_t(vh4, a + 16384);
                ldsm_x4_t(vl4, a + 24576);
                mma16816(o[2 * dv],     ph[ks], vh4[0], vh4[1]);
                mma16816(o[2 * dv],     ph[ks], vl4[0], vl4[1]);
                mma16816(o[2 * dv + 1], ph[ks], vh4[2], vh4[3]);
                mma16816(o[2 * dv + 1], ph[ks], vl4[2], vl4[3]);
            }
        }
    }

    // ---- normalize + write AO fp16 hi ----
    float i0 = 1.0f / l0, i1 = 1.0f / l1;
    int t0 = qt * 64 + wid * 16 + g, t1 = t0 + 8;
#pragma unroll
    for (int nt = 0; nt < 8; nt++) {
        int col = nt * 8 + tig * 2;
        *(uint32_t*)&AOh[base + (size_t)t0 * Ev + col] =
            pack_f16(o[nt][0] * i0, o[nt][1] * i0);
        *(uint32_t*)&AOh[base + (size_t)t1 * Ev + col] =
            pack_f16(o[nt][2] * i1, o[nt][3] * i1);
    }
}

// ---------------------------------------------------------------------------
// Launch
// ---------------------------------------------------------------------------
extern "C" void kernel_launch(void* const* d_in, const int* in_sizes, int n_in,
                              void* d_out, int out_size) {
    const float* x  = (const float*)d_in[0];
    const float* Wq = (const float*)d_in[1];
    const float* Wk = (const float*)d_in[2];
    const float* Wv = (const float*)d_in[3];
    const float* Wo = (const float*)d_in[4];
    float* out = (float*)d_out;

    __half *qh, *khi, *klo, *vhi, *vlo, *aoh, *xh, *wthi, *wtlo;
    cudaGetSymbolAddress((void**)&qh,   g_qh);
    cudaGetSymbolAddress((void**)&khi,  g_khi);
    cudaGetSymbolAddress((void**)&klo,  g_klo);
    cudaGetSymbolAddress((void**)&vhi,  g_vhi);
    cudaGetSymbolAddress((void**)&vlo,  g_vlo);
    cudaGetSymbolAddress((void**)&aoh,  g_aoh);
    cudaGetSymbolAddress((void**)&xh,   g_xh);
    cudaGetSymbolAddress((void**)&wthi, g_wthi);
    cudaGetSymbolAddress((void**)&wtlo, g_wtlo);

    static bool attr_set = false;
    if (!attr_set) {
        cudaFuncSetAttribute(gemm_hmma_f16x2<0>,
                             cudaFuncAttributeMaxDynamicSharedMemorySize, GEMM_SMEM);
        cudaFuncSetAttribute(gemm_hmma_f16x2<1>,
                             cudaFuncAttributeMaxDynamicSharedMemorySize, GEMM_SMEM);
        cudaFuncSetAttribute(attn_hmma,
                             cudaFuncAttributeMaxDynamicSharedMemorySize, ATT_SMEM);
        attr_set = true;
    }

    const int nElem = MTOK * Ev;

    // 1. x -> fp16 hi
    split_hi4<<<nElem / 1024, 256>>>(x, xh, nElem);

    // 2. transpose + split all 4 weights
    dim3 tGrid(Ev / 32, Ev / 32, 4), tBlk(32, 8);
    transpose_split4<<<tGrid, tBlk>>>(Wq, Wk, Wv, Wo, wthi, wtlo);

    // 3. fused QKV projection (N = 3072)
    dim3 qkvGrid(24, MTOK / BM);
    gemm_hmma_f16x2<1><<<qkvGrid, 256, GEMM_SMEM>>>(
        xh, wthi, wtlo, nullptr, qh, khi, klo, vhi, vlo);

    // 4. flash attention (3 CTAs/SM)
    dim3 attnGrid(Sv / 64, Bv * Hv);   // (32, 32)
    attn_hmma<<<attnGrid, 128, ATT_SMEM>>>(qh, khi, klo, vhi, vlo, aoh);

    // 5. output projection -> fp32 out
    dim3 oGrid(Ev / BN, MTOK / BM);
    gemm_hmma_f16x2<0><<<oGrid, 256, GEMM_SMEM>>>(
        aoh, wthi, wtlo, out, nullptr, nullptr, nullptr, nullptr, nullptr);
}

// round 10
// speedup vs baseline: 6.2238x; 1.0559x over previous
#include <cuda_runtime.h>
#include <cuda_fp16.h>
#include <cstdint>

// Problem constants
#define Bv   2
#define Sv   2048
#define Hv   16
#define Dv   64
#define Ev   1024
#define MTOK (Bv * Sv)   // 4096 tokens
#define EE   (Ev * Ev)

// ---------------------------------------------------------------------------
// Scratch (device globals — no allocation allowed)
// ---------------------------------------------------------------------------
__device__ __half g_qh [MTOK * Ev];
__device__ __half g_khi[MTOK * Ev], g_klo[MTOK * Ev];
__device__ __half g_vhi[MTOK * Ev];
__device__ __half g_aoh[MTOK * Ev];
__device__ __half g_xh [MTOK * Ev];
__device__ __half g_wthi[4][EE];   // W^T fp16 hi  [N,K]
__device__ __half g_wtlo[4][EE];   // W^T fp16 lo  [N,K]

// ---------------------------------------------------------------------------
// PTX helpers
// ---------------------------------------------------------------------------
__device__ __forceinline__ uint32_t smem_to_u32(const void* p) {
    uint32_t a;
    asm("{ .reg .u64 t; cvta.to.shared.u64 t, %1; cvt.u32.u64 %0, t; }"
        : "=r"(a) : "l"(p));
    return a;
}
__device__ __forceinline__ void cp_async16(uint32_t smem, const void* gmem) {
    asm volatile("cp.async.cg.shared.global [%0], [%1], 16;"
                 :: "r"(smem), "l"(gmem));
}
#define CP_COMMIT() asm volatile("cp.async.commit_group;" ::: "memory")
#define CP_WAIT1()  asm volatile("cp.async.wait_group 1;"  ::: "memory")

__device__ __forceinline__ void ldsm_x4(uint32_t* r, uint32_t addr) {
    asm volatile("ldmatrix.sync.aligned.m8n8.x4.shared.b16 {%0,%1,%2,%3}, [%4];"
                 : "=r"(r[0]), "=r"(r[1]), "=r"(r[2]), "=r"(r[3]) : "r"(addr));
}
__device__ __forceinline__ void ldsm_x4_t(uint32_t* r, uint32_t addr) {
    asm volatile("ldmatrix.sync.aligned.m8n8.x4.trans.shared.b16 {%0,%1,%2,%3}, [%4];"
                 : "=r"(r[0]), "=r"(r[1]), "=r"(r[2]), "=r"(r[3]) : "r"(addr));
}
__device__ __forceinline__ void mma16816(float* d, const uint32_t* a,
                                         uint32_t b0, uint32_t b1) {
    asm volatile(
        "mma.sync.aligned.m16n8k16.row.col.f32.f16.f16.f32 "
        "{%0,%1,%2,%3}, {%4,%5,%6,%7}, {%8,%9}, {%0,%1,%2,%3};"
        : "+f"(d[0]), "+f"(d[1]), "+f"(d[2]), "+f"(d[3])
        : "r"(a[0]), "r"(a[1]), "r"(a[2]), "r"(a[3]), "r"(b0), "r"(b1));
}
// {lo: rn(a), hi: rn(b)} fp16x2 pack
__device__ __forceinline__ uint32_t pack_f16(float a, float b) {
    uint32_t r;
    asm("cvt.rn.f16x2.f32 %0, %1, %2;" : "=r"(r) : "f"(b), "f"(a));
    return r;
}
__device__ __forceinline__ float2 unpack_f16(uint32_t p) {
    __half2 h = *reinterpret_cast<__half2*>(&p);
    return __half22float2(h);
}
__device__ __forceinline__ float ex2(float x) {
    float r; asm("ex2.approx.f32 %0, %1;" : "=f"(r) : "f"(x)); return r;
}

// ---------------------------------------------------------------------------
// fp32 -> fp16 (hi only), vectorized
// ---------------------------------------------------------------------------
__global__ __launch_bounds__(256) void split_hi4(const float* __restrict__ in,
                                                 __half* __restrict__ hi, int n) {
    int i = (blockIdx.x * 256 + threadIdx.x) * 4;
    if (i < n) {
        float4 v = *(const float4*)(in + i);
        *(uint2*)(hi + i) = make_uint2(pack_f16(v.x, v.y), pack_f16(v.z, v.w));
    }
}

// ---------------------------------------------------------------------------
// Transpose + fp16 hi/lo split, all 4 weights in one launch
// ---------------------------------------------------------------------------
__global__ __launch_bounds__(256) void transpose_split4(
    const float* __restrict__ W0, const float* __restrict__ W1,
    const float* __restrict__ W2, const float* __restrict__ W3,
    __half* __restrict__ ThiB, __half* __restrict__ TloB) {
    __shared__ float t[32][33];
    const float* W = (blockIdx.z == 0) ? W0 : (blockIdx.z == 1) ? W1
                    : (blockIdx.z == 2) ? W2 : W3;
    __half* Thi = ThiB + (size_t)blockIdx.z * EE;
    __half* Tlo = TloB + (size_t)blockIdx.z * EE;
    int n0 = blockIdx.x * 32, k0 = blockIdx.y * 32;
    int tx = threadIdx.x, ty = threadIdx.y;
    for (int i = ty; i < 32; i += 8)
        t[i][tx] = W[(size_t)(k0 + i) * Ev + n0 + tx];
    __syncthreads();
    for (int i = ty; i < 32; i += 8) {
        float v = t[tx][i];
        __half h = __float2half_rn(v);
        size_t idx = (size_t)(n0 + i) * Ev + k0 + tx;
        Thi[idx] = h;
        Tlo[idx] = __float2half_rn(v - __half2float(h));
    }
}

// ---------------------------------------------------------------------------
// HMMA GEMM fp16x2 (B-side compensated): C = A @ B^T,
// D = Ahi*Bhi + Ahi*Blo. 128x128x32 tile, 3-stage cp.async, 8 warps, 2 CTAs/SM.
// MODE 0: out-projection (W index 3), fp32 C out.
// MODE 1: fused QKV (w = bx>>3): w0 -> Q hi; w1 -> K hi/lo; w2 -> V hi only.
// ---------------------------------------------------------------------------
#define BM 128
#define BN 128
#define BK 32
#define STAGES 3
#define TILE_B  8192u                 // 128*32*2B
#define STAGE_B (3u * TILE_B)         // Ahi, Bhi, Blo
#define GEMM_SMEM (STAGES * STAGE_B)  // 72 KB
#define NCHUNK (Ev / BK)              // 32

template <int MODE>
__global__ __launch_bounds__(256, 2) void gemm_hmma_f16x2(
    const __half* __restrict__ Ah,
    const __half* __restrict__ WThi, const __half* __restrict__ WTlo,
    float* __restrict__ C,
    __half* __restrict__ O0h,
    __half* __restrict__ O1h, __half* __restrict__ O1l,
    __half* __restrict__ O2h) {
    extern __shared__ char smc[];
    const uint32_t sbase = smem_to_u32(smc);
    const int tid  = threadIdx.x;
    const int lane = tid & 31;
    const int wid  = tid >> 5;
    const int warp_m = wid & 1;
    const int warp_n = wid >> 1;
    const int m0 = blockIdx.y * BM;
    const int K = Ev, N = Ev;

    const __half *Bhi, *Blo;
    int n0, w = 0;
    if (MODE == 0) {
        Bhi = WThi + (size_t)3 * EE;
        Blo = WTlo + (size_t)3 * EE;
        n0 = blockIdx.x * BN;
    } else {
        w = blockIdx.x >> 3;
        n0 = (blockIdx.x & 7) * BN;
        Bhi = WThi + (size_t)w * EE;
        Blo = WTlo + (size_t)w * EE;
    }

    auto load_stage = [&](int kc, int s) {
        uint32_t st = sbase + (uint32_t)s * STAGE_B;
#pragma unroll
        for (int half = 0; half < 2; half++) {
            int q   = tid + half * 256;
            int row = q >> 2;
            int ch  = q & 3;
            uint32_t sw = (uint32_t)(row * 64 + ((ch ^ ((row >> 1) & 3)) * 16));
            size_t ga = (size_t)(m0 + row) * K + kc * BK + ch * 8;
            size_t gb = (size_t)(n0 + row) * K + kc * BK + ch * 8;
            cp_async16(st + sw,              Ah  + ga);
            cp_async16(st + 8192 + sw,       Bhi + gb);
            cp_async16(st + 16384 + sw,      Blo + gb);
        }
    };

    float acc[4][4][4];
#pragma unroll
    for (int mt = 0; mt < 4; mt++)
#pragma unroll
        for (int nt = 0; nt < 4; nt++)
#pragma unroll
            for (int e = 0; e < 4; e++) acc[mt][nt][e] = 0.0f;

    load_stage(0, 0); CP_COMMIT();
    load_stage(1, 1); CP_COMMIT();

    const int sub = lane >> 3;
    const int r8  = lane & 7;

    for (int c = 0; c < NCHUNK; c++) {
        CP_WAIT1();
        __syncthreads();
        uint32_t st = sbase + (uint32_t)(c % STAGES) * STAGE_B;

#pragma unroll
        for (int ks = 0; ks < 2; ks++) {
            const int ch = ks * 2 + (sub >> 1);
            uint32_t ah[4][4];
#pragma unroll
            for (int mt = 0; mt < 4; mt++) {
                int row = warp_m * 64 + mt * 16 + (sub & 1) * 8 + r8;
                ldsm_x4(ah[mt], st + (uint32_t)(row * 64 + ((ch ^ ((row >> 1) & 3)) * 16)));
            }
            uint32_t bhi[2][4], blo[2][4];
#pragma unroll
            for (int np = 0; np < 2; np++) {
                int row = warp_n * 32 + np * 16 + (sub & 1) * 8 + r8;
                uint32_t addr = st + 8192 +
                                (uint32_t)(row * 64 + ((ch ^ ((row >> 1) & 3)) * 16));
                ldsm_x4(bhi[np], addr);
                ldsm_x4(blo[np], addr + 8192);
            }
#pragma unroll
            for (int mt = 0; mt < 4; mt++)
#pragma unroll
                for (int nt = 0; nt < 4; nt++) {
                    uint32_t b0h = bhi[nt >> 1][nt & 1], b1h = bhi[nt >> 1][2 + (nt & 1)];
                    uint32_t b0l = blo[nt >> 1][nt & 1], b1l = blo[nt >> 1][2 + (nt & 1)];
                    mma16816(acc[mt][nt], ah[mt], b0h, b1h);
                    mma16816(acc[mt][nt], ah[mt], b0l, b1l);
                }
        }
        __syncthreads();
        if (c + STAGES - 1 < NCHUNK) load_stage(c + STAGES - 1, (c + STAGES - 1) % STAGES);
        CP_COMMIT();
    }

    const int g   = lane >> 2;
    const int tig = lane & 3;
    __half* Chi = nullptr;
    if (MODE == 1) Chi = (w == 0) ? O0h : (w == 1) ? O1h : O2h;
#pragma unroll
    for (int mt = 0; mt < 4; mt++) {
        int r0 = m0 + warp_m * 64 + mt * 16 + g;
#pragma unroll
        for (int nt = 0; nt < 4; nt++) {
            int col = n0 + warp_n * 32 + nt * 8 + tig * 2;
            float* a = acc[mt][nt];
            if (MODE == 1) {
                uint32_t h0 = pack_f16(a[0], a[1]);
                uint32_t h1 = pack_f16(a[2], a[3]);
                *(uint32_t*)&Chi[(size_t)r0 * N + col]       = h0;
                *(uint32_t*)&Chi[(size_t)(r0 + 8) * N + col] = h1;
                if (w == 1) {   // only K needs a compensation term
                    float2 v0 = unpack_f16(h0), v1 = unpack_f16(h1);
                    *(uint32_t*)&O1l[(size_t)r0 * N + col] =
                        pack_f16(a[0] - v0.x, a[1] - v0.y);
                    *(uint32_t*)&O1l[(size_t)(r0 + 8) * N + col] =
                        pack_f16(a[2] - v1.x, a[3] - v1.y);
                }
            } else {
                *(float2*)&C[(size_t)r0 * N + col]       = make_float2(a[0], a[1]);
                *(float2*)&C[(size_t)(r0 + 8) * N + col] = make_float2(a[2], a[3]);
            }
        }
    }
}

// ---------------------------------------------------------------------------
// HMMA flash attention (causal). 128 threads (4 warps x 16 q-rows = 64 q-rows),
// KV tile 64, 2-stage. Smem: Q 8K | 2 x (Khi Klo Vhi @8K) = 56 KB, 3 CTAs/SM.
// S = Qh*Khi + Qh*Klo ; P fp16 (rn) ; O += Ph*Vhi (V uncompensated).
// Row sums come from an extra MMA with B = ones (off the critical path).
// ---------------------------------------------------------------------------
#define ATT_STAGE 24576
#define ATT_SMEM (8192 + 2 * ATT_STAGE)   // 56 KB
#define ONES_H2 0x3C003C00u               // {1.0h, 1.0h}

__global__ __launch_bounds__(128, 3) void attn_hmma(
    const __half* __restrict__ Qh,
    const __half* __restrict__ Khi, const __half* __restrict__ Klo,
    const __half* __restrict__ Vhi,
    __half* __restrict__ AOh) {
    extern __shared__ char smc[];
    const uint32_t sb = smem_to_u32(smc);
    const int tid = threadIdx.x, lane = tid & 31, wid = tid >> 5;
    const int qt = (int)gridDim.x - 1 - (int)blockIdx.x;  // heavy tiles first
    const int bh = blockIdx.y;
    const int b  = bh >> 4, h = bh & 15;
    const size_t base = (size_t)(b * Sv) * Ev + h * Dv;

    const int sub = lane >> 3, r8 = lane & 7, g = lane >> 2, tig = lane & 3;

    const uint32_t sQ = sb;
    auto stage = [&](int s) { return sb + 8192 + (uint32_t)s * ATT_STAGE; };
    auto sw = [](int row, int ch) {
        return (uint32_t)(row * 128 + ((ch ^ (row & 7)) * 16));
    };

    // Q tile (64 rows) — part of cp.async group 0
    {
        const __half* q0 = Qh + base + (size_t)(qt * 64) * Ev;
        for (int i = tid; i < 512; i += 128) {
            int row = i >> 3, ch = i & 7;
            cp_async16(sQ + sw(row, ch), q0 + (size_t)row * Ev + ch * 8);
        }
    }
    auto loadKV = [&](int j, int s) {
        uint32_t st = stage(s);
        const __half* kh = Khi + base + (size_t)(j * 64) * Ev;
        const __half* kl = Klo + base + (size_t)(j * 64) * Ev;
        const __half* vh = Vhi + base + (size_t)(j * 64) * Ev;
#pragma unroll
        for (int rep = 0; rep < 4; rep++) {
            int i = tid + rep * 128;           // 0..511
            int row = i >> 3, ch = i & 7;
            size_t off = (size_t)row * Ev + ch * 8;
            uint32_t d = sw(row, ch);
            cp_async16(st + d,         kh + off);
            cp_async16(st + 8192 + d,  kl + off);
            cp_async16(st + 16384 + d, vh + off);
        }
    };
    loadKV(0, 0); CP_COMMIT();

    const int ntiles = qt + 1;
    const int wr0 = qt * 64 + wid * 16;
    const float Cc = 0.125f * 1.44269504f;     // scale * log2(e)

    float m0 = -1e30f, m1 = -1e30f, l0 = 0.f, l1 = 0.f;
    float o[8][4];
#pragma unroll
    for (int nt = 0; nt < 8; nt++)
#pragma unroll
        for (int e = 0; e < 4; e++) o[nt][e] = 0.f;
    uint32_t qh[4][4];

    for (int j = 0; j < ntiles; j++) {
        __syncthreads();
        if (j + 1 < ntiles) loadKV(j + 1, (j + 1) & 1);
        CP_COMMIT();
        CP_WAIT1();
        __syncthreads();
        uint32_t st = stage(j & 1);

        if (j == 0) {
#pragma unroll
            for (int ks = 0; ks < 4; ks++) {
                int row = wid * 16 + (sub & 1) * 8 + r8;
                int ch  = ks * 2 + (sub >> 1);
                ldsm_x4(qh[ks], sQ + sw(row, ch));
            }
        }

        // ---- S = Q K^T (2-term: K compensated) ----
        float s[8][4];
#pragma unroll
        for (int nt = 0; nt < 8; nt++)
#pragma unroll
            for (int e = 0; e < 4; e++) s[nt][e] = 0.f;

#pragma unroll
        for (int ks = 0; ks < 4; ks++) {
            uint32_t kh4[4][4], kl4[4][4];
#pragma unroll
            for (int np = 0; np < 4; np++) {
                int row = np * 16 + (sub & 1) * 8 + r8;
                int ch  = ks * 2 + (sub >> 1);
                uint32_t a = st + sw(row, ch);
                ldsm_x4(kh4[np], a);
                ldsm_x4(kl4[np], a + 8192);
            }
#pragma unroll
            for (int nt = 0; nt < 8; nt++) {
                uint32_t b0h = kh4[nt >> 1][nt & 1], b1h = kh4[nt >> 1][2 + (nt & 1)];
                uint32_t b0l = kl4[nt >> 1][nt & 1], b1l = kl4[nt >> 1][2 + (nt & 1)];
                mma16816(s[nt], qh[ks], b0h, b1h);
                mma16816(s[nt], qh[ks], b0l, b1l);
            }
        }

        // ---- causal mask (diagonal tile only) ----
        if (j == qt) {
            int colb = j * 64;
            int row0 = wr0 + g, row1 = row0 + 8;
#pragma unroll
            for (int nt = 0; nt < 8; nt++) {
                int c0 = colb + nt * 8 + tig * 2;
                if (c0     > row0) s[nt][0] = -1e30f;
                if (c0 + 1 > row0) s[nt][1] = -1e30f;
                if (c0     > row1) s[nt][2] = -1e30f;
                if (c0 + 1 > row1) s[nt][3] = -1e30f;
            }
        }

        // ---- online softmax: max (quad shuffles), exp, rescale ----
        float mx0 = -1e30f, mx1 = -1e30f;
#pragma unroll
        for (int nt = 0; nt < 8; nt++) {
            mx0 = fmaxf(mx0, fmaxf(s[nt][0], s[nt][1]));
            mx1 = fmaxf(mx1, fmaxf(s[nt][2], s[nt][3]));
        }
        mx0 = fmaxf(mx0, __shfl_xor_sync(0xffffffffu, mx0, 1));
        mx0 = fmaxf(mx0, __shfl_xor_sync(0xffffffffu, mx0, 2));
        mx1 = fmaxf(mx1, __shfl_xor_sync(0xffffffffu, mx1, 1));
        mx1 = fmaxf(mx1, __shfl_xor_sync(0xffffffffu, mx1, 2));
        float nm0 = fmaxf(m0, mx0), nm1 = fmaxf(m1, mx1);
        float cr0 = ex2((m0 - nm0) * Cc), cr1 = ex2((m1 - nm1) * Cc);
        m0 = nm0; m1 = nm1;
#pragma unroll
        for (int nt = 0; nt < 8; nt++) {
            s[nt][0] = ex2((s[nt][0] - m0) * Cc);
            s[nt][1] = ex2((s[nt][1] - m0) * Cc);
            s[nt][2] = ex2((s[nt][2] - m1) * Cc);
            s[nt][3] = ex2((s[nt][3] - m1) * Cc);
        }
#pragma unroll
        for (int nt = 0; nt < 8; nt++) {
            o[nt][0] *= cr0; o[nt][1] *= cr0;
            o[nt][2] *= cr1; o[nt][3] *= cr1;
        }

        // ---- P fragments (fp16 rn, straight from acc layout) ----
        uint32_t ph[4][4];
#pragma unroll
        for (int j2 = 0; j2 < 4; j2++) {
            float* e0 = s[2 * j2];
            float* e1 = s[2 * j2 + 1];
            ph[j2][0] = pack_f16(e0[0], e0[1]);
            ph[j2][1] = pack_f16(e0[2], e0[3]);
            ph[j2][2] = pack_f16(e1[0], e1[1]);
            ph[j2][3] = pack_f16(e1[2], e1[3]);
        }

        // ---- row sums via MMA with B = ones (exact over the fp16 P used
        //      in PV; no shuffles; off the critical path) ----
        float ls[4] = {0.f, 0.f, 0.f, 0.f};
#pragma unroll
        for (int ks = 0; ks < 4; ks++)
            mma16816(ls, ph[ks], ONES_H2, ONES_H2);
        l0 = l0 * cr0 + ls[0];
        l1 = l1 * cr1 + ls[2];

        // ---- O += P Vhi (single term; ldmatrix.trans) ----
#pragma unroll
        for (int ks = 0; ks < 4; ks++) {
#pragma unroll
            for (int dv = 0; dv < 4; dv++) {
                int row = ks * 16 + (sub & 1) * 8 + r8;
                int ch  = dv * 2 + (sub >> 1);
                uint32_t vh4[4];
                ldsm_x4_t(vh4, st + sw(row, ch) + 16384);
                mma16816(o[2 * dv],     ph[ks], vh4[0], vh4[1]);
                mma16816(o[2 * dv + 1], ph[ks], vh4[2], vh4[3]);
            }
        }
    }

    // ---- normalize + write AO fp16 ----
    float i0 = 1.0f / l0, i1 = 1.0f / l1;
    int t0 = qt * 64 + wid * 16 + g, t1 = t0 + 8;
#pragma unroll
    for (int nt = 0; nt < 8; nt++) {
        int col = nt * 8 + tig * 2;
        *(uint32_t*)&AOh[base + (size_t)t0 * Ev + col] =
            pack_f16(o[nt][0] * i0, o[nt][1] * i0);
        *(uint32_t*)&AOh[base + (size_t)t1 * Ev + col] =
            pack_f16(o[nt][2] * i1, o[nt][3] * i1);
    }
}

// ---------------------------------------------------------------------------
// Launch
// ---------------------------------------------------------------------------
extern "C" void kernel_launch(void* const* d_in, const int* in_sizes, int n_in,
                              void* d_out, int out_size) {
    const float* x  = (const float*)d_in[0];
    const float* Wq = (const float*)d_in[1];
    const float* Wk = (const float*)d_in[2];
    const float* Wv = (const float*)d_in[3];
    const float* Wo = (const float*)d_in[4];
    float* out = (float*)d_out;

    __half *qh, *khi, *klo, *vhi, *aoh, *xh, *wthi, *wtlo;
    cudaGetSymbolAddress((void**)&qh,   g_qh);
    cudaGetSymbolAddress((void**)&khi,  g_khi);
    cudaGetSymbolAddress((void**)&klo,  g_klo);
    cudaGetSymbolAddress((void**)&vhi,  g_vhi);
    cudaGetSymbolAddress((void**)&aoh,  g_aoh);
    cudaGetSymbolAddress((void**)&xh,   g_xh);
    cudaGetSymbolAddress((void**)&wthi, g_wthi);
    cudaGetSymbolAddress((void**)&wtlo, g_wtlo);

    static bool attr_set = false;
    if (!attr_set) {
        cudaFuncSetAttribute(gemm_hmma_f16x2<0>,
                             cudaFuncAttributeMaxDynamicSharedMemorySize, GEMM_SMEM);
        cudaFuncSetAttribute(gemm_hmma_f16x2<1>,
                             cudaFuncAttributeMaxDynamicSharedMemorySize, GEMM_SMEM);
        cudaFuncSetAttribute(attn_hmma,
                             cudaFuncAttributeMaxDynamicSharedMemorySize, ATT_SMEM);
        attr_set = true;
    }

    const int nElem = MTOK * Ev;

    // 1. x -> fp16
    split_hi4<<<nElem / 1024, 256>>>(x, xh, nElem);

    // 2. transpose + split all 4 weights
    dim3 tGrid(Ev / 32, Ev / 32, 4), tBlk(32, 8);
    transpose_split4<<<tGrid, tBlk>>>(Wq, Wk, Wv, Wo, wthi, wtlo);

    // 3. fused QKV projection (N = 3072)
    dim3 qkvGrid(24, MTOK / BM);
    gemm_hmma_f16x2<1><<<qkvGrid, 256, GEMM_SMEM>>>(
        xh, wthi, wtlo, nullptr, qh, khi, klo, vhi);

    // 4. flash attention
    dim3 attnGrid(Sv / 64, Bv * Hv);   // (32, 32)
    attn_hmma<<<attnGrid, 128, ATT_SMEM>>>(qh, khi, klo, vhi, aoh);

    // 5. output projection -> fp32 out
    dim3 oGrid(Ev / BN, MTOK / BM);
    gemm_hmma_f16x2<0><<<oGrid, 256, GEMM_SMEM>>>(
        aoh, wthi, wtlo, out, nullptr, nullptr, nullptr, nullptr);
}

// round 11
// speedup vs baseline: 7.1958x; 1.1562x over previous
#include <cuda_runtime.h>
#include <cuda_fp16.h>
#include <cstdint>

// Problem constants
#define Bv   2
#define Sv   2048
#define Hv   16
#define Dv   64
#define Ev   1024
#define MTOK (Bv * Sv)   // 4096 tokens
#define EE   (Ev * Ev)

// ---------------------------------------------------------------------------
// Scratch (device globals — no allocation allowed)
// ---------------------------------------------------------------------------
__device__ __half g_qh [MTOK * Ev];
__device__ __half g_khi[MTOK * Ev], g_klo[MTOK * Ev];
__device__ __half g_vhi[MTOK * Ev];
__device__ __half g_aoh[MTOK * Ev];
__device__ __half g_xh [MTOK * Ev];
__device__ __half g_wthi[4][EE];   // W^T fp16 hi  [N,K]
__device__ __half g_wtlo[4][EE];   // W^T fp16 lo  [N,K] (used for Wq, Wk only)

// ---------------------------------------------------------------------------
// PTX helpers
// ---------------------------------------------------------------------------
__device__ __forceinline__ uint32_t smem_to_u32(const void* p) {
    uint32_t a;
    asm("{ .reg .u64 t; cvta.to.shared.u64 t, %1; cvt.u32.u64 %0, t; }"
        : "=r"(a) : "l"(p));
    return a;
}
__device__ __forceinline__ void cp_async16(uint32_t smem, const void* gmem) {
    asm volatile("cp.async.cg.shared.global [%0], [%1], 16;"
                 :: "r"(smem), "l"(gmem));
}
#define CP_COMMIT() asm volatile("cp.async.commit_group;" ::: "memory")
#define CP_WAIT1()  asm volatile("cp.async.wait_group 1;"  ::: "memory")

__device__ __forceinline__ void ldsm_x4(uint32_t* r, uint32_t addr) {
    asm volatile("ldmatrix.sync.aligned.m8n8.x4.shared.b16 {%0,%1,%2,%3}, [%4];"
                 : "=r"(r[0]), "=r"(r[1]), "=r"(r[2]), "=r"(r[3]) : "r"(addr));
}
__device__ __forceinline__ void ldsm_x4_t(uint32_t* r, uint32_t addr) {
    asm volatile("ldmatrix.sync.aligned.m8n8.x4.trans.shared.b16 {%0,%1,%2,%3}, [%4];"
                 : "=r"(r[0]), "=r"(r[1]), "=r"(r[2]), "=r"(r[3]) : "r"(addr));
}
__device__ __forceinline__ void mma16816(float* d, const uint32_t* a,
                                         uint32_t b0, uint32_t b1) {
    asm volatile(
        "mma.sync.aligned.m16n8k16.row.col.f32.f16.f16.f32 "
        "{%0,%1,%2,%3}, {%4,%5,%6,%7}, {%8,%9}, {%0,%1,%2,%3};"
        : "+f"(d[0]), "+f"(d[1]), "+f"(d[2]), "+f"(d[3])
        : "r"(a[0]), "r"(a[1]), "r"(a[2]), "r"(a[3]), "r"(b0), "r"(b1));
}
// {lo: rn(a), hi: rn(b)} fp16x2 pack
__device__ __forceinline__ uint32_t pack_f16(float a, float b) {
    uint32_t r;
    asm("cvt.rn.f16x2.f32 %0, %1, %2;" : "=r"(r) : "f"(b), "f"(a));
    return r;
}
__device__ __forceinline__ float2 unpack_f16(uint32_t p) {
    __half2 h = *reinterpret_cast<__half2*>(&p);
    return __half22float2(h);
}
__device__ __forceinline__ float ex2(float x) {
    float r; asm("ex2.approx.f32 %0, %1;" : "=f"(r) : "f"(x)); return r;
}
// two fp16 2^x in one MUFU op
__device__ __forceinline__ uint32_t ex2h2(uint32_t a) {
    uint32_t r; asm("ex2.approx.f16x2 %0, %1;" : "=r"(r) : "r"(a)); return r;
}

// ---------------------------------------------------------------------------
// fp32 -> fp16, vectorized
// ---------------------------------------------------------------------------
__global__ __launch_bounds__(256) void split_hi4(const float* __restrict__ in,
                                                 __half* __restrict__ hi, int n) {
    int i = (blockIdx.x * 256 + threadIdx.x) * 4;
    if (i < n) {
        float4 v = *(const float4*)(in + i);
        *(uint2*)(hi + i) = make_uint2(pack_f16(v.x, v.y), pack_f16(v.z, v.w));
    }
}

// ---------------------------------------------------------------------------
// Transpose + fp16 hi/lo split, all 4 weights in one launch
// ---------------------------------------------------------------------------
__global__ __launch_bounds__(256) void transpose_split4(
    const float* __restrict__ W0, const float* __restrict__ W1,
    const float* __restrict__ W2, const float* __restrict__ W3,
    __half* __restrict__ ThiB, __half* __restrict__ TloB) {
    __shared__ float t[32][33];
    const float* W = (blockIdx.z == 0) ? W0 : (blockIdx.z == 1) ? W1
                    : (blockIdx.z == 2) ? W2 : W3;
    __half* Thi = ThiB + (size_t)blockIdx.z * EE;
    __half* Tlo = TloB + (size_t)blockIdx.z * EE;
    int n0 = blockIdx.x * 32, k0 = blockIdx.y * 32;
    int tx = threadIdx.x, ty = threadIdx.y;
    for (int i = ty; i < 32; i += 8)
        t[i][tx] = W[(size_t)(k0 + i) * Ev + n0 + tx];
    __syncthreads();
    for (int i = ty; i < 32; i += 8) {
        float v = t[tx][i];
        __half h = __float2half_rn(v);
        size_t idx = (size_t)(n0 + i) * Ev + k0 + tx;
        Thi[idx] = h;
        Tlo[idx] = __float2half_rn(v - __half2float(h));
    }
}

// ---------------------------------------------------------------------------
// HMMA GEMM fp16 (optionally B-compensated): C = A @ B^T.
// D = Ah*Bhi (+ Ah*Blo when the weight is compensated).
// 128x128x32 tile, 3-stage cp.async, 8 warps, 2 CTAs/SM.
// MODE 0: out-projection (W index 3, UNcompensated), fp32 C out.
// MODE 1: fused QKV (w = bx>>3): w0=Q (comp), w1=K (comp, hi/lo out),
//         w2=V (UNcompensated, hi out).
// ---------------------------------------------------------------------------
#define BM 128
#define BN 128
#define BK 32
#define STAGES 3
#define TILE_B  8192u                 // 128*32*2B
#define STAGE_B (3u * TILE_B)         // Ah, Bhi, Blo
#define GEMM_SMEM (STAGES * STAGE_B)  // 72 KB
#define NCHUNK (Ev / BK)              // 32

template <int MODE>
__global__ __launch_bounds__(256, 2) void gemm_hmma_f16x2(
    const __half* __restrict__ Ah,
    const __half* __restrict__ WThi, const __half* __restrict__ WTlo,
    float* __restrict__ C,
    __half* __restrict__ O0h,
    __half* __restrict__ O1h, __half* __restrict__ O1l,
    __half* __restrict__ O2h) {
    extern __shared__ char smc[];
    const uint32_t sbase = smem_to_u32(smc);
    const int tid  = threadIdx.x;
    const int lane = tid & 31;
    const int wid  = tid >> 5;
    const int warp_m = wid & 1;
    const int warp_n = wid >> 1;
    const int m0 = blockIdx.y * BM;
    const int K = Ev, N = Ev;

    const __half *Bhi, *Blo;
    int n0, w = 0;
    bool use_lo;
    if (MODE == 0) {
        Bhi = WThi + (size_t)3 * EE;
        Blo = WTlo + (size_t)3 * EE;
        n0 = blockIdx.x * BN;
        use_lo = false;                   // Wo uncompensated
    } else {
        w = blockIdx.x >> 3;
        n0 = (blockIdx.x & 7) * BN;
        Bhi = WThi + (size_t)w * EE;
        Blo = WTlo + (size_t)w * EE;
        use_lo = (w != 2);                // Wv uncompensated
    }

    auto load_stage = [&](int kc, int s) {
        uint32_t st = sbase + (uint32_t)s * STAGE_B;
#pragma unroll
        for (int half = 0; half < 2; half++) {
            int q   = tid + half * 256;
            int row = q >> 2;
            int ch  = q & 3;
            uint32_t sw = (uint32_t)(row * 64 + ((ch ^ ((row >> 1) & 3)) * 16));
            size_t ga = (size_t)(m0 + row) * K + kc * BK + ch * 8;
            size_t gb = (size_t)(n0 + row) * K + kc * BK + ch * 8;
            cp_async16(st + sw,         Ah  + ga);
            cp_async16(st + 8192 + sw,  Bhi + gb);
            if (use_lo) cp_async16(st + 16384 + sw, Blo + gb);
        }
    };

    float acc[4][4][4];
#pragma unroll
    for (int mt = 0; mt < 4; mt++)
#pragma unroll
        for (int nt = 0; nt < 4; nt++)
#pragma unroll
            for (int e = 0; e < 4; e++) acc[mt][nt][e] = 0.0f;

    load_stage(0, 0); CP_COMMIT();
    load_stage(1, 1); CP_COMMIT();

    const int sub = lane >> 3;
    const int r8  = lane & 7;

    for (int c = 0; c < NCHUNK; c++) {
        CP_WAIT1();
        __syncthreads();
        uint32_t st = sbase + (uint32_t)(c % STAGES) * STAGE_B;

#pragma unroll
        for (int ks = 0; ks < 2; ks++) {
            const int ch = ks * 2 + (sub >> 1);
            uint32_t ah[4][4];
#pragma unroll
            for (int mt = 0; mt < 4; mt++) {
                int row = warp_m * 64 + mt * 16 + (sub & 1) * 8 + r8;
                ldsm_x4(ah[mt], st + (uint32_t)(row * 64 + ((ch ^ ((row >> 1) & 3)) * 16)));
            }
            uint32_t bhi[2][4], blo[2][4];
#pragma unroll
            for (int np = 0; np < 2; np++) {
                int row = warp_n * 32 + np * 16 + (sub & 1) * 8 + r8;
                uint32_t addr = st + 8192 +
                                (uint32_t)(row * 64 + ((ch ^ ((row >> 1) & 3)) * 16));
                ldsm_x4(bhi[np], addr);
                if (use_lo) ldsm_x4(blo[np], addr + 8192);
            }
#pragma unroll
            for (int mt = 0; mt < 4; mt++)
#pragma unroll
                for (int nt = 0; nt < 4; nt++) {
                    uint32_t b0h = bhi[nt >> 1][nt & 1], b1h = bhi[nt >> 1][2 + (nt & 1)];
                    mma16816(acc[mt][nt], ah[mt], b0h, b1h);
                    if (use_lo) {
                        uint32_t b0l = blo[nt >> 1][nt & 1], b1l = blo[nt >> 1][2 + (nt & 1)];
                        mma16816(acc[mt][nt], ah[mt], b0l, b1l);
                    }
                }
        }
        __syncthreads();
        if (c + STAGES - 1 < NCHUNK) load_stage(c + STAGES - 1, (c + STAGES - 1) % STAGES);
        CP_COMMIT();
    }

    const int g   = lane >> 2;
    const int tig = lane & 3;
    __half* Chi = nullptr;
    if (MODE == 1) Chi = (w == 0) ? O0h : (w == 1) ? O1h : O2h;
#pragma unroll
    for (int mt = 0; mt < 4; mt++) {
        int r0 = m0 + warp_m * 64 + mt * 16 + g;
#pragma unroll
        for (int nt = 0; nt < 4; nt++) {
            int col = n0 + warp_n * 32 + nt * 8 + tig * 2;
            float* a = acc[mt][nt];
            if (MODE == 1) {
                uint32_t h0 = pack_f16(a[0], a[1]);
                uint32_t h1 = pack_f16(a[2], a[3]);
                *(uint32_t*)&Chi[(size_t)r0 * N + col]       = h0;
                *(uint32_t*)&Chi[(size_t)(r0 + 8) * N + col] = h1;
                if (w == 1) {   // only K output needs a compensation term
                    float2 v0 = unpack_f16(h0), v1 = unpack_f16(h1);
                    *(uint32_t*)&O1l[(size_t)r0 * N + col] =
                        pack_f16(a[0] - v0.x, a[1] - v0.y);
                    *(uint32_t*)&O1l[(size_t)(r0 + 8) * N + col] =
                        pack_f16(a[2] - v1.x, a[3] - v1.y);
                }
            } else {
                *(float2*)&C[(size_t)r0 * N + col]       = make_float2(a[0], a[1]);
                *(float2*)&C[(size_t)(r0 + 8) * N + col] = make_float2(a[2], a[3]);
            }
        }
    }
}

// ---------------------------------------------------------------------------
// HMMA flash attention (causal). 128 threads (4 warps x 16 q-rows = 64 q-rows),
// KV tile 64, 2-stage. Smem: Q 8K | 2 x (Khi Klo Vhi @8K) = 56 KB, 3 CTAs/SM.
// S = Qh*Khi + Qh*Klo ; P via ex2.approx.f16x2 (P IS the exp output) ;
// O += Ph*Vhi. Row sums via MMA with B = ones (off the critical path).
// ---------------------------------------------------------------------------
#define ATT_STAGE 24576
#define ATT_SMEM (8192 + 2 * ATT_STAGE)   // 56 KB
#define ONES_H2 0x3C003C00u               // {1.0h, 1.0h}

__global__ __launch_bounds__(128, 3) void attn_hmma(
    const __half* __restrict__ Qh,
    const __half* __restrict__ Khi, const __half* __restrict__ Klo,
    const __half* __restrict__ Vhi,
    __half* __restrict__ AOh) {
    extern __shared__ char smc[];
    const uint32_t sb = smem_to_u32(smc);
    const int tid = threadIdx.x, lane = tid & 31, wid = tid >> 5;
    const int qt = (int)gridDim.x - 1 - (int)blockIdx.x;  // heavy tiles first
    const int bh = blockIdx.y;
    const int b  = bh >> 4, h = bh & 15;
    const size_t base = (size_t)(b * Sv) * Ev + h * Dv;

    const int sub = lane >> 3, r8 = lane & 7, g = lane >> 2, tig = lane & 3;

    const uint32_t sQ = sb;
    auto stage = [&](int s) { return sb + 8192 + (uint32_t)s * ATT_STAGE; };
    auto sw = [](int row, int ch) {
        return (uint32_t)(row * 128 + ((ch ^ (row & 7)) * 16));
    };

    // Q tile (64 rows) — part of cp.async group 0
    {
        const __half* q0 = Qh + base + (size_t)(qt * 64) * Ev;
        for (int i = tid; i < 512; i += 128) {
            int row = i >> 3, ch = i & 7;
            cp_async16(sQ + sw(row, ch), q0 + (size_t)row * Ev + ch * 8);
        }
    }
    auto loadKV = [&](int j, int s) {
        uint32_t st = stage(s);
        const __half* kh = Khi + base + (size_t)(j * 64) * Ev;
        const __half* kl = Klo + base + (size_t)(j * 64) * Ev;
        const __half* vh = Vhi + base + (size_t)(j * 64) * Ev;
#pragma unroll
        for (int rep = 0; rep < 4; rep++) {
            int i = tid + rep * 128;           // 0..511
            int row = i >> 3, ch = i & 7;
            size_t off = (size_t)row * Ev + ch * 8;
            uint32_t d = sw(row, ch);
            cp_async16(st + d,         kh + off);
            cp_async16(st + 8192 + d,  kl + off);
            cp_async16(st + 16384 + d, vh + off);
        }
    };
    loadKV(0, 0); CP_COMMIT();

    const int ntiles = qt + 1;
    const int wr0 = qt * 64 + wid * 16;
    const float Cc = 0.125f * 1.44269504f;     // scale * log2(e)

    float m0 = -1e30f, m1 = -1e30f, l0 = 0.f, l1 = 0.f;
    float o[8][4];
#pragma unroll
    for (int nt = 0; nt < 8; nt++)
#pragma unroll
        for (int e = 0; e < 4; e++) o[nt][e] = 0.f;
    uint32_t qh[4][4];

    for (int j = 0; j < ntiles; j++) {
        __syncthreads();
        if (j + 1 < ntiles) loadKV(j + 1, (j + 1) & 1);
        CP_COMMIT();
        CP_WAIT1();
        __syncthreads();
        uint32_t st = stage(j & 1);

        if (j == 0) {
#pragma unroll
            for (int ks = 0; ks < 4; ks++) {
                int row = wid * 16 + (sub & 1) * 8 + r8;
                int ch  = ks * 2 + (sub >> 1);
                ldsm_x4(qh[ks], sQ + sw(row, ch));
            }
        }

        // ---- S = Q K^T (2-term: K compensated) ----
        float s[8][4];
#pragma unroll
        for (int nt = 0; nt < 8; nt++)
#pragma unroll
            for (int e = 0; e < 4; e++) s[nt][e] = 0.f;

#pragma unroll
        for (int ks = 0; ks < 4; ks++) {
            uint32_t kh4[4][4], kl4[4][4];
#pragma unroll
            for (int np = 0; np < 4; np++) {
                int row = np * 16 + (sub & 1) * 8 + r8;
                int ch  = ks * 2 + (sub >> 1);
                uint32_t a = st + sw(row, ch);
                ldsm_x4(kh4[np], a);
                ldsm_x4(kl4[np], a + 8192);
            }
#pragma unroll
            for (int nt = 0; nt < 8; nt++) {
                uint32_t b0h = kh4[nt >> 1][nt & 1], b1h = kh4[nt >> 1][2 + (nt & 1)];
                uint32_t b0l = kl4[nt >> 1][nt & 1], b1l = kl4[nt >> 1][2 + (nt & 1)];
                mma16816(s[nt], qh[ks], b0h, b1h);
                mma16816(s[nt], qh[ks], b0l, b1l);
            }
        }

        // ---- causal mask (diagonal tile only) ----
        if (j == qt) {
            int colb = j * 64;
            int row0 = wr0 + g, row1 = row0 + 8;
#pragma unroll
            for (int nt = 0; nt < 8; nt++) {
                int c0 = colb + nt * 8 + tig * 2;
                if (c0     > row0) s[nt][0] = -1e30f;
                if (c0 + 1 > row0) s[nt][1] = -1e30f;
                if (c0     > row1) s[nt][2] = -1e30f;
                if (c0 + 1 > row1) s[nt][3] = -1e30f;
            }
        }

        // ---- online softmax: row max (quad shuffles) + rescale factors ----
        float mx0 = -1e30f, mx1 = -1e30f;
#pragma unroll
        for (int nt = 0; nt < 8; nt++) {
            mx0 = fmaxf(mx0, fmaxf(s[nt][0], s[nt][1]));
            mx1 = fmaxf(mx1, fmaxf(s[nt][2], s[nt][3]));
        }
        mx0 = fmaxf(mx0, __shfl_xor_sync(0xffffffffu, mx0, 1));
        mx0 = fmaxf(mx0, __shfl_xor_sync(0xffffffffu, mx0, 2));
        mx1 = fmaxf(mx1, __shfl_xor_sync(0xffffffffu, mx1, 1));
        mx1 = fmaxf(mx1, __shfl_xor_sync(0xffffffffu, mx1, 2));
        float nm0 = fmaxf(m0, mx0), nm1 = fmaxf(m1, mx1);
        float cr0 = ex2((m0 - nm0) * Cc), cr1 = ex2((m1 - nm1) * Cc);
        m0 = nm0; m1 = nm1;
        const float mm0 = m0 * Cc, mm1 = m1 * Cc;

        // ---- P fragments: arg in fp32 (FFMA), pack, exp in f16x2 ----
        uint32_t ph[4][4];
#pragma unroll
        for (int j2 = 0; j2 < 4; j2++) {
            float* e0 = s[2 * j2];
            float* e1 = s[2 * j2 + 1];
            ph[j2][0] = ex2h2(pack_f16(fmaf(e0[0], Cc, -mm0), fmaf(e0[1], Cc, -mm0)));
            ph[j2][1] = ex2h2(pack_f16(fmaf(e0[2], Cc, -mm1), fmaf(e0[3], Cc, -mm1)));
            ph[j2][2] = ex2h2(pack_f16(fmaf(e1[0], Cc, -mm0), fmaf(e1[1], Cc, -mm0)));
            ph[j2][3] = ex2h2(pack_f16(fmaf(e1[2], Cc, -mm1), fmaf(e1[3], Cc, -mm1)));
        }

        // ---- rescale O ----
#pragma unroll
        for (int nt = 0; nt < 8; nt++) {
            o[nt][0] *= cr0; o[nt][1] *= cr0;
            o[nt][2] *= cr1; o[nt][3] *= cr1;
        }

        // ---- row sums via MMA with B = ones (off the critical path) ----
        float ls[4] = {0.f, 0.f, 0.f, 0.f};
#pragma unroll
        for (int ks = 0; ks < 4; ks++)
            mma16816(ls, ph[ks], ONES_H2, ONES_H2);
        l0 = l0 * cr0 + ls[0];
        l1 = l1 * cr1 + ls[2];

        // ---- O += P Vhi (ldmatrix.trans) ----
#pragma unroll
        for (int ks = 0; ks < 4; ks++) {
#pragma unroll
            for (int dv = 0; dv < 4; dv++) {
                int row = ks * 16 + (sub & 1) * 8 + r8;
                int ch  = dv * 2 + (sub >> 1);
                uint32_t vh4[4];
                ldsm_x4_t(vh4, st + sw(row, ch) + 16384);
                mma16816(o[2 * dv],     ph[ks], vh4[0], vh4[1]);
                mma16816(o[2 * dv + 1], ph[ks], vh4[2], vh4[3]);
            }
        }
    }

    // ---- normalize + write AO fp16 ----
    float i0 = 1.0f / l0, i1 = 1.0f / l1;
    int t0 = qt * 64 + wid * 16 + g, t1 = t0 + 8;
#pragma unroll
    for (int nt = 0; nt < 8; nt++) {
        int col = nt * 8 + tig * 2;
        *(uint32_t*)&AOh[base + (size_t)t0 * Ev + col] =
            pack_f16(o[nt][0] * i0, o[nt][1] * i0);
        *(uint32_t*)&AOh[base + (size_t)t1 * Ev + col] =
            pack_f16(o[nt][2] * i1, o[nt][3] * i1);
    }
}

// ---------------------------------------------------------------------------
// Launch
// ---------------------------------------------------------------------------
extern "C" void kernel_launch(void* const* d_in, const int* in_sizes, int n_in,
                              void* d_out, int out_size) {
    const float* x  = (const float*)d_in[0];
    const float* Wq = (const float*)d_in[1];
    const float* Wk = (const float*)d_in[2];
    const float* Wv = (const float*)d_in[3];
    const float* Wo = (const float*)d_in[4];
    float* out = (float*)d_out;

    __half *qh, *khi, *klo, *vhi, *aoh, *xh, *wthi, *wtlo;
    cudaGetSymbolAddress((void**)&qh,   g_qh);
    cudaGetSymbolAddress((void**)&khi,  g_khi);
    cudaGetSymbolAddress((void**)&klo,  g_klo);
    cudaGetSymbolAddress((void**)&vhi,  g_vhi);
    cudaGetSymbolAddress((void**)&aoh,  g_aoh);
    cudaGetSymbolAddress((void**)&xh,   g_xh);
    cudaGetSymbolAddress((void**)&wthi, g_wthi);
    cudaGetSymbolAddress((void**)&wtlo, g_wtlo);

    static bool attr_set = false;
    if (!attr_set) {
        cudaFuncSetAttribute(gemm_hmma_f16x2<0>,
                             cudaFuncAttributeMaxDynamicSharedMemorySize, GEMM_SMEM);
        cudaFuncSetAttribute(gemm_hmma_f16x2<1>,
                             cudaFuncAttributeMaxDynamicSharedMemorySize, GEMM_SMEM);
        cudaFuncSetAttribute(attn_hmma,
                             cudaFuncAttributeMaxDynamicSharedMemorySize, ATT_SMEM);
        attr_set = true;
    }

    const int nElem = MTOK * Ev;

    // 1. x -> fp16
    split_hi4<<<nElem / 1024, 256>>>(x, xh, nElem);

    // 2. transpose + split all 4 weights
    dim3 tGrid(Ev / 32, Ev / 32, 4), tBlk(32, 8);
    transpose_split4<<<tGrid, tBlk>>>(Wq, Wk, Wv, Wo, wthi, wtlo);

    // 3. fused QKV projection (N = 3072)
    dim3 qkvGrid(24, MTOK / BM);
    gemm_hmma_f16x2<1><<<qkvGrid, 256, GEMM_SMEM>>>(
        xh, wthi, wtlo, nullptr, qh, khi, klo, vhi);

    // 4. flash attention
    dim3 attnGrid(Sv / 64, Bv * Hv);   // (32, 32)
    attn_hmma<<<attnGrid, 128, ATT_SMEM>>>(qh, khi, klo, vhi, aoh);

    // 5. output projection -> fp32 out
    dim3 oGrid(Ev / BN, MTOK / BM);
    gemm_hmma_f16x2<0><<<oGrid, 256, GEMM_SMEM>>>(
        aoh, wthi, wtlo, out, nullptr, nullptr, nullptr, nullptr);
}